// round 6
// baseline (speedup 1.0000x reference)
#include <cuda_runtime.h>
#include <cuda_bf16.h>
#include <cstdint>

#define N_NODES   100000
#define E_PER_REL 150000
#define R_REL     4
#define E_TOTAL   (E_PER_REL * R_REL)
#define WC_COLS   320   // [self(64) | rel0(64) | rel1(64) | rel2(64) | rel3(64)]

// ---------------------------------------------------------------------------
// Device globals (no runtime allocation allowed)
// ---------------------------------------------------------------------------
__device__ __align__(128) float g_Y1[(size_t)N_NODES * WC_COLS];   // 128 MB
__device__ __align__(128) float g_Y2[(size_t)N_NODES * WC_COLS];   // 128 MB
// Pre-swizzled bf16 weight tiles: [cb*CHUNKS+ch] tiles of 64n x 64k (8192 B)
__device__ __align__(256) __nv_bfloat16 g_B1h[5 * 2 * 64 * 64];
__device__ __align__(256) __nv_bfloat16 g_B1l[5 * 2 * 64 * 64];
__device__ __align__(256) __nv_bfloat16 g_B2h[5 * 1 * 64 * 64];
__device__ __align__(256) __nv_bfloat16 g_B2l[5 * 1 * 64 * 64];
__device__ int2 g_eoff[E_TOTAL];   // per-edge {src msg float-offset, dst acc float-offset}
__device__ int g_idx_is64;

// XOR swizzle on 16B granules within a 128B row: byte offset for (row, k)
__device__ __forceinline__ uint32_t swz(uint32_t row, uint32_t k) {
    uint32_t g = k >> 3;
    return row * 128u + (((g ^ (row & 7u)) << 4) | ((k & 7u) << 1));
}

// ---------------------------------------------------------------------------
// Index-dtype sniff: int64 values < 2^31 => every odd 32-bit word is zero.
// ---------------------------------------------------------------------------
__global__ void sniff_kernel(const unsigned int* __restrict__ idx) {
    __shared__ int nz;
    if (threadIdx.x == 0) nz = 0;
    __syncthreads();
    for (int i = threadIdx.x; i < 4096; i += blockDim.x)
        if (idx[2 * i + 1] != 0u) nz = 1;
    __syncthreads();
    if (threadIdx.x == 0) g_idx_is64 = (nz == 0) ? 1 : 0;
}

// ---------------------------------------------------------------------------
// Bake per-edge float offsets: src -> message slot (incl. relation), dst -> acc.
// ---------------------------------------------------------------------------
__global__ void prep_idx_kernel(const void* __restrict__ src_v,
                                const void* __restrict__ dst_v,
                                int2* __restrict__ eoff) {
    int e = blockIdx.x * blockDim.x + threadIdx.x;
    if (e >= E_TOTAL) return;
    int r = e / E_PER_REL;
    int s, d;
    if (g_idx_is64) {
        s = (int)((const long long*)src_v)[e];
        d = (int)((const long long*)dst_v)[e];
    } else {
        s = ((const int*)src_v)[e];
        d = ((const int*)dst_v)[e];
    }
    eoff[e] = make_int2(s * WC_COLS + 64 + r * 64, d * WC_COLS);
}

// ---------------------------------------------------------------------------
// Weight prep: combined signed weights -> swizzled bf16 hi/lo tiles.
// ---------------------------------------------------------------------------
__global__ void prep_w_kernel(const float* __restrict__ Wrel,
                              const float* __restrict__ Wself,
                              __nv_bfloat16* __restrict__ Bh,
                              __nv_bfloat16* __restrict__ Bl,
                              int din, int chunks) {
    int idx = blockIdx.x * blockDim.x + threadIdx.x;   // c * din + d
    if (idx >= WC_COLS * din) return;
    int c = idx / din;
    int d = idx - c * din;
    float v;
    if (c < 64) {
        v = Wself[d * 64 + c];
    } else {
        int r = (c - 64) >> 6;
        int o = (c - 64) & 63;
        v = Wrel[((size_t)r * din + d) * 64 + o];
        if (r == 3) v = -v;   // SUBTRACT_REL = 3
    }
    __nv_bfloat16 hi = __float2bfloat16(v);
    __nv_bfloat16 lo = __float2bfloat16(v - __bfloat162float(hi));
    int cb = c >> 6, n = c & 63;
    int ch = d >> 6, k = d & 63;
    size_t tile = (size_t)(cb * chunks + ch) * 8192;   // bytes
    uint32_t off = swz((uint32_t)n, (uint32_t)k);
    *(__nv_bfloat16*)((char*)Bh + tile + off) = hi;
    *(__nv_bfloat16*)((char*)Bl + tile + off) = lo;
}

// ---------------------------------------------------------------------------
// mma.sync m16n8k16 bf16 (row.col), f32 accumulate — base PTX, works on sm_103
// ---------------------------------------------------------------------------
__device__ __forceinline__ void mma16816(float* c, const uint32_t* a, uint32_t b0, uint32_t b1) {
    asm volatile("mma.sync.aligned.m16n8k16.row.col.f32.bf16.bf16.f32 "
                 "{%0,%1,%2,%3}, {%4,%5,%6,%7}, {%8,%9}, {%0,%1,%2,%3};"
                 : "+f"(c[0]), "+f"(c[1]), "+f"(c[2]), "+f"(c[3])
                 : "r"(a[0]), "r"(a[1]), "r"(a[2]), "r"(a[3]), "r"(b0), "r"(b1));
}
__device__ __forceinline__ void ldsm4(uint32_t* r, uint32_t addr) {
    asm volatile("ldmatrix.sync.aligned.m8n8.x4.shared.b16 {%0,%1,%2,%3}, [%4];"
                 : "=r"(r[0]), "=r"(r[1]), "=r"(r[2]), "=r"(r[3]) : "r"(addr));
}

// ---------------------------------------------------------------------------
// Tensor-core GEMM: C[M,320] = A[M, CHUNKS*64] @ Wc.
// CTA = 128 rows; A loaded/converted ONCE into smem, then 5 column blocks
// computed in-CTA (reuse). 8 warps as 4(m) x 2(n); warp tile 32m x 32n.
// bf16 3-MMA split, f32 accum in registers.
// ---------------------------------------------------------------------------
template <int CHUNKS, bool RELU>
__global__ void __launch_bounds__(256, 2) gemm_mma_kernel(const float* __restrict__ A, int lda,
                                                          const __nv_bfloat16* __restrict__ Bh,
                                                          const __nv_bfloat16* __restrict__ Bl,
                                                          float* __restrict__ C) {
    extern __shared__ char smem[];
    __nv_bfloat16* Ah  = (__nv_bfloat16*)smem;                     // CHUNKS*8192 elems
    __nv_bfloat16* Al  = Ah + CHUNKS * 128 * 64;
    __nv_bfloat16* Bhs = Al + CHUNKS * 128 * 64;                   // 64x64
    __nv_bfloat16* Bls = Bhs + 64 * 64;

    const int tid  = threadIdx.x;
    const int wid  = tid >> 5;
    const int lane = tid & 31;
    const int m0   = blockIdx.x * 128;
    const int wm   = wid >> 1;        // 0..3 (m quarter)
    const int wn   = wid & 1;         // 0..1 (n half)

    const uint32_t ah_u = (uint32_t)__cvta_generic_to_shared(Ah);
    const uint32_t al_u = (uint32_t)__cvta_generic_to_shared(Al);
    const uint32_t bh_u = (uint32_t)__cvta_generic_to_shared(Bhs);
    const uint32_t bl_u = (uint32_t)__cvta_generic_to_shared(Bls);

    // ldmatrix lane geometry
    const int tq = lane >> 3;
    const int lr = lane & 7;
    const int a_lrow = lr + (tq & 1) * 8;   // + wm*32 + mt*16
    const int a_gad  = (tq >> 1);
    const int b_lr   = lr + (tq >> 1) * 8;  // + wn*32 + bt*16
    const int b_gad  = (tq & 1);

    // ---- Load + convert A (all chunks) f32 -> bf16 hi/lo, swizzled. Once.
#pragma unroll
    for (int i = 0; i < CHUNKS * 4; i++) {
        int gran = i * 256 + tid;          // 1024 granules/chunk of 8 k-values
        int ch  = gran >> 10;
        int rem = gran & 1023;
        int m = rem >> 3;
        int g = rem & 7;
        int gr = m0 + m;
        float4 v0 = make_float4(0.f, 0.f, 0.f, 0.f), v1 = v0;
        if (gr < N_NODES) {
            const float* ap = &A[(size_t)gr * lda + ch * 64 + g * 8];
            v0 = *(const float4*)ap;
            v1 = *(const float4*)(ap + 4);
            if (RELU) {
                v0.x = fmaxf(v0.x, 0.f); v0.y = fmaxf(v0.y, 0.f);
                v0.z = fmaxf(v0.z, 0.f); v0.w = fmaxf(v0.w, 0.f);
                v1.x = fmaxf(v1.x, 0.f); v1.y = fmaxf(v1.y, 0.f);
                v1.z = fmaxf(v1.z, 0.f); v1.w = fmaxf(v1.w, 0.f);
            }
        }
        float f[8] = {v0.x, v0.y, v0.z, v0.w, v1.x, v1.y, v1.z, v1.w};
        __nv_bfloat16 h[8], l[8];
#pragma unroll
        for (int j = 0; j < 8; j++) {
            h[j] = __float2bfloat16(f[j]);
            l[j] = __float2bfloat16(f[j] - __bfloat162float(h[j]));
        }
        uint32_t off = (uint32_t)(ch * 16384) + swz((uint32_t)m, (uint32_t)(g * 8));
        *(uint4*)((char*)Ah + off) = *(const uint4*)h;
        *(uint4*)((char*)Al + off) = *(const uint4*)l;
    }

    for (int cb = 0; cb < 5; cb++) {
        float acc[2][4][4];
#pragma unroll
        for (int mt = 0; mt < 2; mt++)
#pragma unroll
            for (int j = 0; j < 4; j++)
#pragma unroll
                for (int q = 0; q < 4; q++) acc[mt][j][q] = 0.f;

        for (int ch = 0; ch < CHUNKS; ch++) {
            __syncthreads();   // previous B readers done (and A stores, first iter)
            {   // copy pre-swizzled B tile (8 KB hi + 8 KB lo)
                size_t tile = (size_t)(cb * CHUNKS + ch) * 8192;
                const uint4* sh = (const uint4*)((const char*)Bh + tile);
                const uint4* sl = (const uint4*)((const char*)Bl + tile);
                uint4* dh = (uint4*)Bhs;
                uint4* dl = (uint4*)Bls;
                dh[tid] = sh[tid]; dh[tid + 256] = sh[tid + 256];
                dl[tid] = sl[tid]; dl[tid + 256] = sl[tid + 256];
            }
            __syncthreads();

#pragma unroll
            for (int ks = 0; ks < 4; ks++) {
                uint32_t afh[2][4], afl[2][4];
#pragma unroll
                for (int mt = 0; mt < 2; mt++) {
                    int arow = wm * 32 + mt * 16 + a_lrow;
                    uint32_t a_off = (uint32_t)(ch * 16384) + arow * 128u +
                                     (((uint32_t)((ks * 2 + a_gad) ^ (arow & 7))) << 4);
                    ldsm4(afh[mt], ah_u + a_off);
                    ldsm4(afl[mt], al_u + a_off);
                }
                uint32_t bfh[2][4], bfl[2][4];
#pragma unroll
                for (int bt = 0; bt < 2; bt++) {
                    int brow = wn * 32 + bt * 16 + b_lr;
                    uint32_t b_off = brow * 128u +
                                     (((uint32_t)((ks * 2 + b_gad) ^ (brow & 7))) << 4);
                    ldsm4(bfh[bt], bh_u + b_off);
                    ldsm4(bfl[bt], bl_u + b_off);
                }
#pragma unroll
                for (int mt = 0; mt < 2; mt++)
#pragma unroll
                    for (int bt = 0; bt < 2; bt++) {
                        float* c0 = acc[mt][bt * 2 + 0];
                        float* c1 = acc[mt][bt * 2 + 1];
                        mma16816(c0, afh[mt], bfh[bt][0], bfh[bt][1]);
                        mma16816(c0, afh[mt], bfl[bt][0], bfl[bt][1]);
                        mma16816(c0, afl[mt], bfh[bt][0], bfh[bt][1]);
                        mma16816(c1, afh[mt], bfh[bt][2], bfh[bt][3]);
                        mma16816(c1, afh[mt], bfl[bt][2], bfl[bt][3]);
                        mma16816(c1, afl[mt], bfh[bt][2], bfh[bt][3]);
                    }
            }
        }

        // ---- Epilogue for this column block (registers -> global)
        const int ccol = (lane & 3) * 2;
#pragma unroll
        for (int mt = 0; mt < 2; mt++) {
            int gr0 = m0 + wm * 32 + mt * 16 + (lane >> 2);
            int gr1 = gr0 + 8;
#pragma unroll
            for (int j = 0; j < 4; j++) {
                int gc = cb * 64 + wn * 32 + j * 8 + ccol;
                if (gr0 < N_NODES)
                    *(float2*)&C[(size_t)gr0 * WC_COLS + gc] =
                        make_float2(acc[mt][j][0], acc[mt][j][1]);
                if (gr1 < N_NODES)
                    *(float2*)&C[(size_t)gr1 * WC_COLS + gc] =
                        make_float2(acc[mt][j][2], acc[mt][j][3]);
            }
        }
    }
}

// ---------------------------------------------------------------------------
// Scatter: Y[dst][0:64] += Y[src][msg slot]  (signs pre-folded into weights)
// 16 threads/edge; offsets pre-baked; 8B index load per 16 lanes + shfl bcast.
// ---------------------------------------------------------------------------
__global__ void __launch_bounds__(256) scatter_kernel(const int2* __restrict__ eoff,
                                                      float* __restrict__ Y) {
    int gid  = blockIdx.x * blockDim.x + threadIdx.x;
    int edge = gid >> 4;
    if (edge >= E_TOTAL) return;
    int sub  = gid & 15;
    int lane = threadIdx.x & 31;

    int2 eo = make_int2(0, 0);
    if ((lane & 15) == 0) eo = __ldg(&eoff[edge]);
    int so = __shfl_sync(0xffffffffu, eo.x, 0, 16);
    int dо = __shfl_sync(0xffffffffu, eo.y, 0, 16);

    const float4 v = *(const float4*)&Y[(size_t)so + sub * 4];
    float* p = &Y[(size_t)dо + sub * 4];
    asm volatile("red.global.add.v4.f32 [%0], {%1,%2,%3,%4};"
                 :: "l"(p), "f"(v.x), "f"(v.y), "f"(v.z), "f"(v.w) : "memory");
}

// ---------------------------------------------------------------------------
// out = sigmoid(relu(Y2[:, 0:64]))
// ---------------------------------------------------------------------------
__global__ void __launch_bounds__(256) sigmoid_kernel(const float* __restrict__ Y,
                                                      float* __restrict__ out) {
    int idx = blockIdx.x * blockDim.x + threadIdx.x;
    if (idx >= N_NODES * 16) return;
    int n  = idx >> 4;
    int c4 = idx & 15;
    float4 v = *(const float4*)&Y[(size_t)n * WC_COLS + c4 * 4];
    v.x = 1.f / (1.f + __expf(-fmaxf(v.x, 0.f)));
    v.y = 1.f / (1.f + __expf(-fmaxf(v.y, 0.f)));
    v.z = 1.f / (1.f + __expf(-fmaxf(v.z, 0.f)));
    v.w = 1.f / (1.f + __expf(-fmaxf(v.w, 0.f)));
    *(float4*)&out[(size_t)n * 64 + c4 * 4] = v;
}

// ---------------------------------------------------------------------------
extern "C" void kernel_launch(void* const* d_in, const int* in_sizes, int n_in,
                              void* d_out, int out_size) {
    const float* node_emb = (const float*)d_in[0];
    const void*  src      = d_in[1];
    const void*  dst      = d_in[2];
    const float* W1       = (const float*)d_in[3];
    const float* Wself1   = (const float*)d_in[4];
    const float* W2       = (const float*)d_in[5];
    const float* Wself2   = (const float*)d_in[6];
    float*       out      = (float*)d_out;

    float *Y1, *Y2;
    __nv_bfloat16 *B1h, *B1l, *B2h, *B2l;
    int2* eoff;
    cudaGetSymbolAddress((void**)&Y1, g_Y1);
    cudaGetSymbolAddress((void**)&Y2, g_Y2);
    cudaGetSymbolAddress((void**)&B1h, g_B1h);
    cudaGetSymbolAddress((void**)&B1l, g_B1l);
    cudaGetSymbolAddress((void**)&B2h, g_B2h);
    cudaGetSymbolAddress((void**)&B2l, g_B2l);
    cudaGetSymbolAddress((void**)&eoff, g_eoff);

    const int smem1 = (2 * 128 * 64 * 2) * 2 + 2 * 64 * 64 * 2;   // 81920
    const int smem2 = (1 * 128 * 64 * 2) * 2 + 2 * 64 * 64 * 2;   // 49152
    cudaFuncSetAttribute(gemm_mma_kernel<2, false>,
                         cudaFuncAttributeMaxDynamicSharedMemorySize, smem1);
    cudaFuncSetAttribute(gemm_mma_kernel<1, true>,
                         cudaFuncAttributeMaxDynamicSharedMemorySize, smem2);

    sniff_kernel<<<1, 256>>>((const unsigned int*)src);
    prep_idx_kernel<<<(E_TOTAL + 255) / 256, 256>>>(src, dst, eoff);
    prep_w_kernel<<<(WC_COLS * 128 + 255) / 256, 256>>>(W1, Wself1, B1h, B1l, 128, 2);
    prep_w_kernel<<<(WC_COLS * 64 + 255) / 256, 256>>>(W2, Wself2, B2h, B2l, 64, 1);

    const int mblocks = (N_NODES + 127) / 128;   // 782
    const int sblocks = (E_TOTAL * 16 + 255) / 256;

    // Layer 1: Y1 = node_emb @ Wc1; scatter messages into Y1[:,0:64]
    gemm_mma_kernel<2, false><<<mblocks, 256, smem1>>>(node_emb, 128, B1h, B1l, Y1);
    scatter_kernel<<<sblocks, 256>>>(eoff, Y1);

    // Layer 2: Y2 = relu(Y1[:,0:64]) @ Wc2; scatter into Y2[:,0:64]
    gemm_mma_kernel<1, true><<<mblocks, 256, smem2>>>(Y1, WC_COLS, B2h, B2l, Y2);
    scatter_kernel<<<sblocks, 256>>>(eoff, Y2);

    // out = sigmoid(relu(Y2[:,0:64]))
    sigmoid_kernel<<<(N_NODES * 16 + 255) / 256, 256>>>(Y2, out);
}

// round 7
// speedup vs baseline: 1.3035x; 1.3035x over previous
#include <cuda_runtime.h>
#include <cuda_bf16.h>
#include <cstdint>

#define N_NODES   100000
#define E_PER_REL 150000
#define R_REL     4
#define E_TOTAL   (E_PER_REL * R_REL)
#define WC_COLS   320   // [self(64) | rel0(64) | rel1(64) | rel2(64) | rel3(64)]

// ---------------------------------------------------------------------------
// Device globals (no runtime allocation allowed)
// ---------------------------------------------------------------------------
__device__ __align__(128) float g_Y1[(size_t)N_NODES * WC_COLS];   // 128 MB
__device__ __align__(128) float g_Y2[(size_t)N_NODES * WC_COLS];   // 128 MB
// Pre-swizzled bf16 weight tiles: [cb*CHUNKS+ch] tiles of 64n x 64k (8192 B)
__device__ __align__(256) __nv_bfloat16 g_B1h[5 * 2 * 64 * 64];
__device__ __align__(256) __nv_bfloat16 g_B1l[5 * 2 * 64 * 64];
__device__ __align__(256) __nv_bfloat16 g_B2h[5 * 1 * 64 * 64];
__device__ __align__(256) __nv_bfloat16 g_B2l[5 * 1 * 64 * 64];
__device__ int2 g_eoff[E_TOTAL];   // per-edge {src msg float-offset, dst acc float-offset}
__device__ int g_idx_is64;

// XOR swizzle on 16B granules within a 128B row: byte offset for (row, k)
__device__ __forceinline__ uint32_t swz(uint32_t row, uint32_t k) {
    uint32_t g = k >> 3;
    return row * 128u + (((g ^ (row & 7u)) << 4) | ((k & 7u) << 1));
}

// ---------------------------------------------------------------------------
// Index-dtype sniff: int64 values < 2^31 => every odd 32-bit word is zero.
// ---------------------------------------------------------------------------
__global__ void sniff_kernel(const unsigned int* __restrict__ idx) {
    __shared__ int nz;
    if (threadIdx.x == 0) nz = 0;
    __syncthreads();
    for (int i = threadIdx.x; i < 4096; i += blockDim.x)
        if (idx[2 * i + 1] != 0u) nz = 1;
    __syncthreads();
    if (threadIdx.x == 0) g_idx_is64 = (nz == 0) ? 1 : 0;
}

// ---------------------------------------------------------------------------
// Bake per-edge float offsets: src -> message slot (incl. relation), dst -> acc.
// ---------------------------------------------------------------------------
__global__ void prep_idx_kernel(const void* __restrict__ src_v,
                                const void* __restrict__ dst_v,
                                int2* __restrict__ eoff) {
    int e = blockIdx.x * blockDim.x + threadIdx.x;
    if (e >= E_TOTAL) return;
    int r = e / E_PER_REL;
    int s, d;
    if (g_idx_is64) {
        s = (int)((const long long*)src_v)[e];
        d = (int)((const long long*)dst_v)[e];
    } else {
        s = ((const int*)src_v)[e];
        d = ((const int*)dst_v)[e];
    }
    eoff[e] = make_int2(s * WC_COLS + 64 + r * 64, d * WC_COLS);
}

// ---------------------------------------------------------------------------
// Weight prep: combined signed weights -> swizzled bf16 hi/lo tiles.
// ---------------------------------------------------------------------------
__global__ void prep_w_kernel(const float* __restrict__ Wrel,
                              const float* __restrict__ Wself,
                              __nv_bfloat16* __restrict__ Bh,
                              __nv_bfloat16* __restrict__ Bl,
                              int din, int chunks) {
    int idx = blockIdx.x * blockDim.x + threadIdx.x;   // c * din + d
    if (idx >= WC_COLS * din) return;
    int c = idx / din;
    int d = idx - c * din;
    float v;
    if (c < 64) {
        v = Wself[d * 64 + c];
    } else {
        int r = (c - 64) >> 6;
        int o = (c - 64) & 63;
        v = Wrel[((size_t)r * din + d) * 64 + o];
        if (r == 3) v = -v;   // SUBTRACT_REL = 3
    }
    __nv_bfloat16 hi = __float2bfloat16(v);
    __nv_bfloat16 lo = __float2bfloat16(v - __bfloat162float(hi));
    int cb = c >> 6, n = c & 63;
    int ch = d >> 6, k = d & 63;
    size_t tile = (size_t)(cb * chunks + ch) * 8192;   // bytes
    uint32_t off = swz((uint32_t)n, (uint32_t)k);
    *(__nv_bfloat16*)((char*)Bh + tile + off) = hi;
    *(__nv_bfloat16*)((char*)Bl + tile + off) = lo;
}

// ---------------------------------------------------------------------------
// mma.sync m16n8k16 bf16 (row.col), f32 accumulate — base PTX, works on sm_103
// ---------------------------------------------------------------------------
__device__ __forceinline__ void mma16816(float* c, const uint32_t* a, uint32_t b0, uint32_t b1) {
    asm volatile("mma.sync.aligned.m16n8k16.row.col.f32.bf16.bf16.f32 "
                 "{%0,%1,%2,%3}, {%4,%5,%6,%7}, {%8,%9}, {%0,%1,%2,%3};"
                 : "+f"(c[0]), "+f"(c[1]), "+f"(c[2]), "+f"(c[3])
                 : "r"(a[0]), "r"(a[1]), "r"(a[2]), "r"(a[3]), "r"(b0), "r"(b1));
}
__device__ __forceinline__ void ldsm4(uint32_t* r, uint32_t addr) {
    asm volatile("ldmatrix.sync.aligned.m8n8.x4.shared.b16 {%0,%1,%2,%3}, [%4];"
                 : "=r"(r[0]), "=r"(r[1]), "=r"(r[2]), "=r"(r[3]) : "r"(addr));
}

// ---------------------------------------------------------------------------
// Tensor-core GEMM: C[M,320] = A[M, CHUNKS*64] @ Wc.
// CTA = 128m x 64n; cb = blockIdx.x (5), mblock = blockIdx.y.
// Adjacent bids share the same A rows -> A served from L2 after first read.
// 8 warps as 4(m) x 2(n); warp tile 32m x 32n. bf16 3-MMA split, f32 accum.
// ---------------------------------------------------------------------------
template <int CHUNKS, bool RELU>
__global__ void __launch_bounds__(256, 2) gemm_mma_kernel(const float* __restrict__ A, int lda,
                                                          const __nv_bfloat16* __restrict__ Bh,
                                                          const __nv_bfloat16* __restrict__ Bl,
                                                          float* __restrict__ C) {
    __shared__ __nv_bfloat16 Ah[128 * 64];   // 16 KB, swizzled
    __shared__ __nv_bfloat16 Al[128 * 64];   // 16 KB
    __shared__ __nv_bfloat16 Bhs[64 * 64];   // 8 KB
    __shared__ __nv_bfloat16 Bls[64 * 64];   // 8 KB

    const int tid  = threadIdx.x;
    const int wid  = tid >> 5;
    const int lane = tid & 31;
    const int cb   = blockIdx.x;      // column block (0..4)
    const int m0   = blockIdx.y * 128;
    const int wm   = wid >> 1;        // 0..3 (m quarter)
    const int wn   = wid & 1;         // 0..1 (n half)

    const uint32_t ah_u = (uint32_t)__cvta_generic_to_shared(Ah);
    const uint32_t al_u = (uint32_t)__cvta_generic_to_shared(Al);
    const uint32_t bh_u = (uint32_t)__cvta_generic_to_shared(Bhs);
    const uint32_t bl_u = (uint32_t)__cvta_generic_to_shared(Bls);

    // ldmatrix lane geometry
    const int tq = lane >> 3;
    const int lr = lane & 7;
    const int a_lrow = lr + (tq & 1) * 8;   // + wm*32 + mt*16
    const int a_gad  = (tq >> 1);
    const int b_lr   = lr + (tq >> 1) * 8;  // + wn*32 + bt*16
    const int b_gad  = (tq & 1);

    float acc[2][4][4];
#pragma unroll
    for (int mt = 0; mt < 2; mt++)
#pragma unroll
        for (int j = 0; j < 4; j++)
#pragma unroll
            for (int q = 0; q < 4; q++) acc[mt][j][q] = 0.f;

    for (int ch = 0; ch < CHUNKS; ch++) {
        // ---- Copy pre-swizzled B tile (8 KB hi + 8 KB lo)
        {
            size_t tile = (size_t)(cb * CHUNKS + ch) * 8192;
            const uint4* sh = (const uint4*)((const char*)Bh + tile);
            const uint4* sl = (const uint4*)((const char*)Bl + tile);
            uint4* dh = (uint4*)Bhs;
            uint4* dl = (uint4*)Bls;
            dh[tid] = sh[tid]; dh[tid + 256] = sh[tid + 256];
            dl[tid] = sl[tid]; dl[tid + 256] = sl[tid + 256];
        }
        // ---- Load + convert A tile [128m x 64k] f32 -> bf16 hi/lo, swizzled
#pragma unroll
        for (int i = 0; i < 4; i++) {
            int gran = i * 256 + tid;       // 1024 granules of 8 k-values
            int m = gran >> 3;
            int g = gran & 7;
            int gr = m0 + m;
            float4 v0 = make_float4(0.f, 0.f, 0.f, 0.f), v1 = v0;
            if (gr < N_NODES) {
                const float* ap = &A[(size_t)gr * lda + ch * 64 + g * 8];
                v0 = *(const float4*)ap;
                v1 = *(const float4*)(ap + 4);
                if (RELU) {
                    v0.x = fmaxf(v0.x, 0.f); v0.y = fmaxf(v0.y, 0.f);
                    v0.z = fmaxf(v0.z, 0.f); v0.w = fmaxf(v0.w, 0.f);
                    v1.x = fmaxf(v1.x, 0.f); v1.y = fmaxf(v1.y, 0.f);
                    v1.z = fmaxf(v1.z, 0.f); v1.w = fmaxf(v1.w, 0.f);
                }
            }
            float f[8] = {v0.x, v0.y, v0.z, v0.w, v1.x, v1.y, v1.z, v1.w};
            __nv_bfloat16 h[8], l[8];
#pragma unroll
            for (int j = 0; j < 8; j++) {
                h[j] = __float2bfloat16(f[j]);
                l[j] = __float2bfloat16(f[j] - __bfloat162float(h[j]));
            }
            uint32_t off = swz((uint32_t)m, (uint32_t)(g * 8));
            *(uint4*)((char*)Ah + off) = *(const uint4*)h;
            *(uint4*)((char*)Al + off) = *(const uint4*)l;
        }
        __syncthreads();

        // ---- Compute: 4 k-steps of 16
#pragma unroll
        for (int ks = 0; ks < 4; ks++) {
            uint32_t afh[2][4], afl[2][4];
#pragma unroll
            for (int mt = 0; mt < 2; mt++) {
                int arow = wm * 32 + mt * 16 + a_lrow;
                uint32_t a_off = arow * 128u +
                                 (((uint32_t)((ks * 2 + a_gad) ^ (arow & 7))) << 4);
                ldsm4(afh[mt], ah_u + a_off);
                ldsm4(afl[mt], al_u + a_off);
            }
            uint32_t bfh[2][4], bfl[2][4];
#pragma unroll
            for (int bt = 0; bt < 2; bt++) {
                int brow = wn * 32 + bt * 16 + b_lr;
                uint32_t b_off = brow * 128u +
                                 (((uint32_t)((ks * 2 + b_gad) ^ (brow & 7))) << 4);
                ldsm4(bfh[bt], bh_u + b_off);
                ldsm4(bfl[bt], bl_u + b_off);
            }
#pragma unroll
            for (int mt = 0; mt < 2; mt++)
#pragma unroll
                for (int bt = 0; bt < 2; bt++) {
                    float* c0 = acc[mt][bt * 2 + 0];
                    float* c1 = acc[mt][bt * 2 + 1];
                    mma16816(c0, afh[mt], bfh[bt][0], bfh[bt][1]);
                    mma16816(c0, afh[mt], bfl[bt][0], bfl[bt][1]);
                    mma16816(c0, afl[mt], bfh[bt][0], bfh[bt][1]);
                    mma16816(c1, afh[mt], bfh[bt][2], bfh[bt][3]);
                    mma16816(c1, afh[mt], bfl[bt][2], bfl[bt][3]);
                    mma16816(c1, afl[mt], bfh[bt][2], bfh[bt][3]);
                }
        }
        __syncthreads();
    }

    // ---- Epilogue (registers -> global)
    const int ccol = (lane & 3) * 2;
#pragma unroll
    for (int mt = 0; mt < 2; mt++) {
        int gr0 = m0 + wm * 32 + mt * 16 + (lane >> 2);
        int gr1 = gr0 + 8;
#pragma unroll
        for (int j = 0; j < 4; j++) {
            int gc = cb * 64 + wn * 32 + j * 8 + ccol;
            if (gr0 < N_NODES)
                *(float2*)&C[(size_t)gr0 * WC_COLS + gc] =
                    make_float2(acc[mt][j][0], acc[mt][j][1]);
            if (gr1 < N_NODES)
                *(float2*)&C[(size_t)gr1 * WC_COLS + gc] =
                    make_float2(acc[mt][j][2], acc[mt][j][3]);
        }
    }
}

// ---------------------------------------------------------------------------
// Scatter: Y[dst][0:64] += Y[src][msg slot]  (signs pre-folded into weights)
// 16 threads/edge; pre-baked offsets; broadcast int2 load per group.
// ---------------------------------------------------------------------------
__global__ void __launch_bounds__(256) scatter_kernel(const int2* __restrict__ eoff,
                                                      float* __restrict__ Y) {
    int gid  = blockIdx.x * blockDim.x + threadIdx.x;
    int edge = gid >> 4;
    if (edge >= E_TOTAL) return;
    int sub = gid & 15;

    int2 eo = __ldg(&eoff[edge]);   // 16 lanes load the same 8B -> L1 broadcast

    const float4 v = *(const float4*)&Y[(size_t)eo.x + sub * 4];
    float* p = &Y[(size_t)eo.y + sub * 4];
    asm volatile("red.global.add.v4.f32 [%0], {%1,%2,%3,%4};"
                 :: "l"(p), "f"(v.x), "f"(v.y), "f"(v.z), "f"(v.w) : "memory");
}

// ---------------------------------------------------------------------------
// out = sigmoid(relu(Y2[:, 0:64]))
// ---------------------------------------------------------------------------
__global__ void __launch_bounds__(256) sigmoid_kernel(const float* __restrict__ Y,
                                                      float* __restrict__ out) {
    int idx = blockIdx.x * blockDim.x + threadIdx.x;
    if (idx >= N_NODES * 16) return;
    int n  = idx >> 4;
    int c4 = idx & 15;
    float4 v = *(const float4*)&Y[(size_t)n * WC_COLS + c4 * 4];
    v.x = 1.f / (1.f + __expf(-fmaxf(v.x, 0.f)));
    v.y = 1.f / (1.f + __expf(-fmaxf(v.y, 0.f)));
    v.z = 1.f / (1.f + __expf(-fmaxf(v.z, 0.f)));
    v.w = 1.f / (1.f + __expf(-fmaxf(v.w, 0.f)));
    *(float4*)&out[(size_t)n * 64 + c4 * 4] = v;
}

// ---------------------------------------------------------------------------
extern "C" void kernel_launch(void* const* d_in, const int* in_sizes, int n_in,
                              void* d_out, int out_size) {
    const float* node_emb = (const float*)d_in[0];
    const void*  src      = d_in[1];
    const void*  dst      = d_in[2];
    const float* W1       = (const float*)d_in[3];
    const float* Wself1   = (const float*)d_in[4];
    const float* W2       = (const float*)d_in[5];
    const float* Wself2   = (const float*)d_in[6];
    float*       out      = (float*)d_out;

    float *Y1, *Y2;
    __nv_bfloat16 *B1h, *B1l, *B2h, *B2l;
    int2* eoff;
    cudaGetSymbolAddress((void**)&Y1, g_Y1);
    cudaGetSymbolAddress((void**)&Y2, g_Y2);
    cudaGetSymbolAddress((void**)&B1h, g_B1h);
    cudaGetSymbolAddress((void**)&B1l, g_B1l);
    cudaGetSymbolAddress((void**)&B2h, g_B2h);
    cudaGetSymbolAddress((void**)&B2l, g_B2l);
    cudaGetSymbolAddress((void**)&eoff, g_eoff);

    sniff_kernel<<<1, 256>>>((const unsigned int*)src);
    prep_idx_kernel<<<(E_TOTAL + 255) / 256, 256>>>(src, dst, eoff);
    prep_w_kernel<<<(WC_COLS * 128 + 255) / 256, 256>>>(W1, Wself1, B1h, B1l, 128, 2);
    prep_w_kernel<<<(WC_COLS * 64 + 255) / 256, 256>>>(W2, Wself2, B2h, B2l, 64, 1);

    const int mblocks = (N_NODES + 127) / 128;   // 782
    const int sblocks = (E_TOTAL * 16 + 255) / 256;

    // Layer 1: Y1 = node_emb @ Wc1; scatter messages into Y1[:,0:64]
    gemm_mma_kernel<2, false><<<dim3(5, mblocks), 256>>>(node_emb, 128, B1h, B1l, Y1);
    scatter_kernel<<<sblocks, 256>>>(eoff, Y1);

    // Layer 2: Y2 = relu(Y1[:,0:64]) @ Wc2; scatter into Y2[:,0:64]
    gemm_mma_kernel<1, true><<<dim3(5, mblocks), 256>>>(Y1, WC_COLS, B2h, B2l, Y2);
    scatter_kernel<<<sblocks, 256>>>(eoff, Y2);

    // out = sigmoid(relu(Y2[:,0:64]))
    sigmoid_kernel<<<(N_NODES * 16 + 255) / 256, 256>>>(Y2, out);
}

// round 8
// speedup vs baseline: 1.4186x; 1.0883x over previous
#include <cuda_runtime.h>
#include <cuda_fp16.h>
#include <cuda_bf16.h>
#include <cstdint>

#define N_NODES   100000
#define E_PER_REL 150000
#define R_REL     4
#define E_TOTAL   (E_PER_REL * R_REL)
#define MSG_COLS  256
#define ACC_COLS  64

// ---------------------------------------------------------------------------
// Device globals (no runtime allocation allowed)
// ---------------------------------------------------------------------------
__device__ __align__(128) float  g_acc1[(size_t)N_NODES * ACC_COLS];  // 25.6 MB
__device__ __align__(128) float  g_acc2[(size_t)N_NODES * ACC_COLS];  // 25.6 MB
__device__ __align__(128) __half g_msg1[(size_t)N_NODES * MSG_COLS];  // 51.2 MB
__device__ __align__(128) __half g_msg2[(size_t)N_NODES * MSG_COLS];  // 51.2 MB
// Pre-swizzled bf16 weight tiles: [cb*CHUNKS+ch] tiles of 64n x 64k (8192 B)
__device__ __align__(256) __nv_bfloat16 g_B1h[5 * 2 * 64 * 64];
__device__ __align__(256) __nv_bfloat16 g_B1l[5 * 2 * 64 * 64];
__device__ __align__(256) __nv_bfloat16 g_B2h[5 * 1 * 64 * 64];
__device__ __align__(256) __nv_bfloat16 g_B2l[5 * 1 * 64 * 64];
__device__ int2 g_eoff[E_TOTAL];   // {src half-offset into msg, dst float-offset into acc}
__device__ int g_idx_is64;

// XOR swizzle on 16B granules within a 128B row: byte offset for (row, k)
__device__ __forceinline__ uint32_t swz(uint32_t row, uint32_t k) {
    uint32_t g = k >> 3;
    return row * 128u + (((g ^ (row & 7u)) << 4) | ((k & 7u) << 1));
}

// ---------------------------------------------------------------------------
__global__ void sniff_kernel(const unsigned int* __restrict__ idx) {
    __shared__ int nz;
    if (threadIdx.x == 0) nz = 0;
    __syncthreads();
    for (int i = threadIdx.x; i < 4096; i += blockDim.x)
        if (idx[2 * i + 1] != 0u) nz = 1;
    __syncthreads();
    if (threadIdx.x == 0) g_idx_is64 = (nz == 0) ? 1 : 0;
}

__global__ void prep_idx_kernel(const void* __restrict__ src_v,
                                const void* __restrict__ dst_v,
                                int2* __restrict__ eoff) {
    int e = blockIdx.x * blockDim.x + threadIdx.x;
    if (e >= E_TOTAL) return;
    int r = e / E_PER_REL;
    int s, d;
    if (g_idx_is64) {
        s = (int)((const long long*)src_v)[e];
        d = (int)((const long long*)dst_v)[e];
    } else {
        s = ((const int*)src_v)[e];
        d = ((const int*)dst_v)[e];
    }
    eoff[e] = make_int2(s * MSG_COLS + r * 64, d * ACC_COLS);
}

// ---------------------------------------------------------------------------
// Weight prep: combined signed weights -> swizzled bf16 hi/lo tiles.
// Column c: 0..63 = Wself; 64.. = sign_r * Wrel.
// ---------------------------------------------------------------------------
__global__ void prep_w_kernel(const float* __restrict__ Wrel,
                              const float* __restrict__ Wself,
                              __nv_bfloat16* __restrict__ Bh,
                              __nv_bfloat16* __restrict__ Bl,
                              int din, int chunks) {
    int idx = blockIdx.x * blockDim.x + threadIdx.x;   // c * din + d
    if (idx >= 320 * din) return;
    int c = idx / din;
    int d = idx - c * din;
    float v;
    if (c < 64) {
        v = Wself[d * 64 + c];
    } else {
        int r = (c - 64) >> 6;
        int o = (c - 64) & 63;
        v = Wrel[((size_t)r * din + d) * 64 + o];
        if (r == 3) v = -v;   // SUBTRACT_REL = 3
    }
    __nv_bfloat16 hi = __float2bfloat16(v);
    __nv_bfloat16 lo = __float2bfloat16(v - __bfloat162float(hi));
    int cb = c >> 6, n = c & 63;
    int ch = d >> 6, k = d & 63;
    size_t tile = (size_t)(cb * chunks + ch) * 8192;   // bytes
    uint32_t off = swz((uint32_t)n, (uint32_t)k);
    *(__nv_bfloat16*)((char*)Bh + tile + off) = hi;
    *(__nv_bfloat16*)((char*)Bl + tile + off) = lo;
}

// ---------------------------------------------------------------------------
__device__ __forceinline__ void mma16816(float* c, const uint32_t* a, uint32_t b0, uint32_t b1) {
    asm volatile("mma.sync.aligned.m16n8k16.row.col.f32.bf16.bf16.f32 "
                 "{%0,%1,%2,%3}, {%4,%5,%6,%7}, {%8,%9}, {%0,%1,%2,%3};"
                 : "+f"(c[0]), "+f"(c[1]), "+f"(c[2]), "+f"(c[3])
                 : "r"(a[0]), "r"(a[1]), "r"(a[2]), "r"(a[3]), "r"(b0), "r"(b1));
}
__device__ __forceinline__ void ldsm4(uint32_t* r, uint32_t addr) {
    asm volatile("ldmatrix.sync.aligned.m8n8.x4.shared.b16 {%0,%1,%2,%3}, [%4];"
                 : "=r"(r[0]), "=r"(r[1]), "=r"(r[2]), "=r"(r[3]) : "r"(addr));
}

// ---------------------------------------------------------------------------
// Tensor-core GEMM. CTA = 128m x 64n; cb = blockIdx.x (0..4), mblock = blockIdx.y.
// cb 0 -> f32 into acc[N,64]; cb 1..4 -> fp16 into msg[N,256] (smem-staged).
// 8 warps as 4(m) x 2(n); warp tile 32m x 32n. bf16 3-MMA split, f32 accum.
// ---------------------------------------------------------------------------
#define STG_STRIDE 72   // halves per staged row (64 + 8 pad -> 144 B)

template <int CHUNKS, bool RELU>
__global__ void __launch_bounds__(256, 2) gemm_mma_kernel(const float* __restrict__ A, int lda,
                                                          const __nv_bfloat16* __restrict__ Bh,
                                                          const __nv_bfloat16* __restrict__ Bl,
                                                          float* __restrict__ Cacc,
                                                          __half* __restrict__ Cmsg) {
    __shared__ __align__(16) char S[49152];
    __nv_bfloat16* Ah  = (__nv_bfloat16*)(S);             // 16 KB
    __nv_bfloat16* Al  = (__nv_bfloat16*)(S + 16384);     // 16 KB
    __nv_bfloat16* Bhs = (__nv_bfloat16*)(S + 32768);     // 8 KB
    __nv_bfloat16* Bls = (__nv_bfloat16*)(S + 40960);     // 8 KB
    __half* stage = (__half*)S;                           // reused post-compute (18.4 KB)

    const int tid  = threadIdx.x;
    const int wid  = tid >> 5;
    const int lane = tid & 31;
    const int cb   = blockIdx.x;      // column block (0..4)
    const int m0   = blockIdx.y * 128;
    const int wm   = wid >> 1;        // 0..3 (m quarter)
    const int wn   = wid & 1;         // 0..1 (n half)

    const uint32_t ah_u = (uint32_t)__cvta_generic_to_shared(Ah);
    const uint32_t al_u = (uint32_t)__cvta_generic_to_shared(Al);
    const uint32_t bh_u = (uint32_t)__cvta_generic_to_shared(Bhs);
    const uint32_t bl_u = (uint32_t)__cvta_generic_to_shared(Bls);

    // ldmatrix lane geometry
    const int tq = lane >> 3;
    const int lr = lane & 7;
    const int a_lrow = lr + (tq & 1) * 8;
    const int a_gad  = (tq >> 1);
    const int b_lr   = lr + (tq >> 1) * 8;
    const int b_gad  = (tq & 1);

    float acc[2][4][4];
#pragma unroll
    for (int mt = 0; mt < 2; mt++)
#pragma unroll
        for (int j = 0; j < 4; j++)
#pragma unroll
            for (int q = 0; q < 4; q++) acc[mt][j][q] = 0.f;

    for (int ch = 0; ch < CHUNKS; ch++) {
        // ---- Copy pre-swizzled B tile (8 KB hi + 8 KB lo)
        {
            size_t tile = (size_t)(cb * CHUNKS + ch) * 8192;
            const uint4* sh = (const uint4*)((const char*)Bh + tile);
            const uint4* sl = (const uint4*)((const char*)Bl + tile);
            uint4* dh = (uint4*)Bhs;
            uint4* dl = (uint4*)Bls;
            dh[tid] = sh[tid]; dh[tid + 256] = sh[tid + 256];
            dl[tid] = sl[tid]; dl[tid + 256] = sl[tid + 256];
        }
        // ---- Load + convert A tile [128m x 64k] f32 -> bf16 hi/lo, swizzled
#pragma unroll
        for (int i = 0; i < 4; i++) {
            int gran = i * 256 + tid;       // 1024 granules of 8 k-values
            int m = gran >> 3;
            int g = gran & 7;
            int gr = m0 + m;
            float4 v0 = make_float4(0.f, 0.f, 0.f, 0.f), v1 = v0;
            if (gr < N_NODES) {
                const float* ap = &A[(size_t)gr * lda + ch * 64 + g * 8];
                v0 = *(const float4*)ap;
                v1 = *(const float4*)(ap + 4);
                if (RELU) {
                    v0.x = fmaxf(v0.x, 0.f); v0.y = fmaxf(v0.y, 0.f);
                    v0.z = fmaxf(v0.z, 0.f); v0.w = fmaxf(v0.w, 0.f);
                    v1.x = fmaxf(v1.x, 0.f); v1.y = fmaxf(v1.y, 0.f);
                    v1.z = fmaxf(v1.z, 0.f); v1.w = fmaxf(v1.w, 0.f);
                }
            }
            float f[8] = {v0.x, v0.y, v0.z, v0.w, v1.x, v1.y, v1.z, v1.w};
            __nv_bfloat16 h[8], l[8];
#pragma unroll
            for (int j = 0; j < 8; j++) {
                h[j] = __float2bfloat16(f[j]);
                l[j] = __float2bfloat16(f[j] - __bfloat162float(h[j]));
            }
            uint32_t off = swz((uint32_t)m, (uint32_t)(g * 8));
            *(uint4*)((char*)Ah + off) = *(const uint4*)h;
            *(uint4*)((char*)Al + off) = *(const uint4*)l;
        }
        __syncthreads();

        // ---- Compute: 4 k-steps of 16
#pragma unroll
        for (int ks = 0; ks < 4; ks++) {
            uint32_t afh[2][4], afl[2][4];
#pragma unroll
            for (int mt = 0; mt < 2; mt++) {
                int arow = wm * 32 + mt * 16 + a_lrow;
                uint32_t a_off = arow * 128u +
                                 (((uint32_t)((ks * 2 + a_gad) ^ (arow & 7))) << 4);
                ldsm4(afh[mt], ah_u + a_off);
                ldsm4(afl[mt], al_u + a_off);
            }
            uint32_t bfh[2][4], bfl[2][4];
#pragma unroll
            for (int bt = 0; bt < 2; bt++) {
                int brow = wn * 32 + bt * 16 + b_lr;
                uint32_t b_off = brow * 128u +
                                 (((uint32_t)((ks * 2 + b_gad) ^ (brow & 7))) << 4);
                ldsm4(bfh[bt], bh_u + b_off);
                ldsm4(bfl[bt], bl_u + b_off);
            }
#pragma unroll
            for (int mt = 0; mt < 2; mt++)
#pragma unroll
                for (int bt = 0; bt < 2; bt++) {
                    float* c0 = acc[mt][bt * 2 + 0];
                    float* c1 = acc[mt][bt * 2 + 1];
                    mma16816(c0, afh[mt], bfh[bt][0], bfh[bt][1]);
                    mma16816(c0, afh[mt], bfl[bt][0], bfl[bt][1]);
                    mma16816(c0, afl[mt], bfh[bt][0], bfh[bt][1]);
                    mma16816(c1, afh[mt], bfh[bt][2], bfh[bt][3]);
                    mma16816(c1, afh[mt], bfl[bt][2], bfl[bt][3]);
                    mma16816(c1, afl[mt], bfh[bt][2], bfh[bt][3]);
                }
        }
        __syncthreads();
    }

    const int ccol = (lane & 3) * 2;
    if (cb == 0) {
        // ---- f32 epilogue into acc[N,64]
#pragma unroll
        for (int mt = 0; mt < 2; mt++) {
            int gr0 = m0 + wm * 32 + mt * 16 + (lane >> 2);
            int gr1 = gr0 + 8;
#pragma unroll
            for (int j = 0; j < 4; j++) {
                int gc = wn * 32 + j * 8 + ccol;
                if (gr0 < N_NODES)
                    *(float2*)&Cacc[(size_t)gr0 * ACC_COLS + gc] =
                        make_float2(acc[mt][j][0], acc[mt][j][1]);
                if (gr1 < N_NODES)
                    *(float2*)&Cacc[(size_t)gr1 * ACC_COLS + gc] =
                        make_float2(acc[mt][j][2], acc[mt][j][3]);
            }
        }
    } else {
        // ---- fp16 epilogue into msg[N,256], staged for coalesced stores
#pragma unroll
        for (int mt = 0; mt < 2; mt++) {
            int lrow0 = wm * 32 + mt * 16 + (lane >> 2);
#pragma unroll
            for (int j = 0; j < 4; j++) {
                int lc = wn * 32 + j * 8 + ccol;
                *(__half2*)&stage[lrow0 * STG_STRIDE + lc] =
                    __floats2half2_rn(acc[mt][j][0], acc[mt][j][1]);
                *(__half2*)&stage[(lrow0 + 8) * STG_STRIDE + lc] =
                    __floats2half2_rn(acc[mt][j][2], acc[mt][j][3]);
            }
        }
        __syncthreads();
        const int mbase = (cb - 1) * 64;
#pragma unroll
        for (int i = 0; i < 4; i++) {
            int chunk = i * 256 + tid;      // 1024 chunks of 16 B
            int row = chunk >> 3;
            int cc  = chunk & 7;
            int gr = m0 + row;
            if (gr < N_NODES) {
                uint4 v = *(const uint4*)&stage[row * STG_STRIDE + cc * 8];
                *(uint4*)&Cmsg[(size_t)gr * MSG_COLS + mbase + cc * 8] = v;
            }
        }
    }
}

// ---------------------------------------------------------------------------
// Scatter: acc[dst][0:64] += f32(msg[src][r*64:r*64+64])  (signs pre-folded)
// 8 threads/edge; 16B uint4 gather of 8 halves; 2 vector REDs per thread.
// ---------------------------------------------------------------------------
__global__ void __launch_bounds__(256) scatter_kernel(const int2* __restrict__ eoff,
                                                      const __half* __restrict__ msg,
                                                      float* __restrict__ acc) {
    int gid  = blockIdx.x * blockDim.x + threadIdx.x;
    int edge = gid >> 3;
    if (edge >= E_TOTAL) return;
    int sub = gid & 7;

    int2 eo = __ldg(&eoff[edge]);   // 8 lanes load the same 8B -> L1 broadcast

    const __half2* mp = (const __half2*)&msg[(size_t)eo.x + sub * 8];
    float2 f0 = __half22float2(mp[0]);
    float2 f1 = __half22float2(mp[1]);
    float2 f2 = __half22float2(mp[2]);
    float2 f3 = __half22float2(mp[3]);

    float* p = &acc[(size_t)eo.y + sub * 8];
    asm volatile("red.global.add.v4.f32 [%0], {%1,%2,%3,%4};"
                 :: "l"(p), "f"(f0.x), "f"(f0.y), "f"(f1.x), "f"(f1.y) : "memory");
    asm volatile("red.global.add.v4.f32 [%0], {%1,%2,%3,%4};"
                 :: "l"(p + 4), "f"(f2.x), "f"(f2.y), "f"(f3.x), "f"(f3.y) : "memory");
}

// ---------------------------------------------------------------------------
// out = sigmoid(relu(acc2))  — fully contiguous
// ---------------------------------------------------------------------------
__global__ void __launch_bounds__(256) sigmoid_kernel(const float* __restrict__ acc,
                                                      float* __restrict__ out) {
    int idx = blockIdx.x * blockDim.x + threadIdx.x;
    if (idx >= N_NODES * 16) return;
    float4 v = *(const float4*)&acc[(size_t)idx * 4];
    v.x = 1.f / (1.f + __expf(-fmaxf(v.x, 0.f)));
    v.y = 1.f / (1.f + __expf(-fmaxf(v.y, 0.f)));
    v.z = 1.f / (1.f + __expf(-fmaxf(v.z, 0.f)));
    v.w = 1.f / (1.f + __expf(-fmaxf(v.w, 0.f)));
    *(float4*)&out[(size_t)idx * 4] = v;
}

// ---------------------------------------------------------------------------
extern "C" void kernel_launch(void* const* d_in, const int* in_sizes, int n_in,
                              void* d_out, int out_size) {
    const float* node_emb = (const float*)d_in[0];
    const void*  src      = d_in[1];
    const void*  dst      = d_in[2];
    const float* W1       = (const float*)d_in[3];
    const float* Wself1   = (const float*)d_in[4];
    const float* W2       = (const float*)d_in[5];
    const float* Wself2   = (const float*)d_in[6];
    float*       out      = (float*)d_out;

    float *acc1, *acc2;
    __half *msg1, *msg2;
    __nv_bfloat16 *B1h, *B1l, *B2h, *B2l;
    int2* eoff;
    cudaGetSymbolAddress((void**)&acc1, g_acc1);
    cudaGetSymbolAddress((void**)&acc2, g_acc2);
    cudaGetSymbolAddress((void**)&msg1, g_msg1);
    cudaGetSymbolAddress((void**)&msg2, g_msg2);
    cudaGetSymbolAddress((void**)&B1h, g_B1h);
    cudaGetSymbolAddress((void**)&B1l, g_B1l);
    cudaGetSymbolAddress((void**)&B2h, g_B2h);
    cudaGetSymbolAddress((void**)&B2l, g_B2l);
    cudaGetSymbolAddress((void**)&eoff, g_eoff);

    sniff_kernel<<<1, 256>>>((const unsigned int*)src);
    prep_idx_kernel<<<(E_TOTAL + 255) / 256, 256>>>(src, dst, eoff);
    prep_w_kernel<<<(320 * 128 + 255) / 256, 256>>>(W1, Wself1, B1h, B1l, 128, 2);
    prep_w_kernel<<<(320 * 64 + 255) / 256, 256>>>(W2, Wself2, B2h, B2l, 64, 1);

    const int mblocks = (N_NODES + 127) / 128;   // 782
    const int sblocks = (E_TOTAL * 8 + 255) / 256;

    // Layer 1: acc1/msg1 = node_emb @ Wc1; scatter msgs into acc1
    gemm_mma_kernel<2, false><<<dim3(5, mblocks), 256>>>(node_emb, 128, B1h, B1l, acc1, msg1);
    scatter_kernel<<<sblocks, 256>>>(eoff, msg1, acc1);

    // Layer 2: acc2/msg2 = relu(acc1) @ Wc2; scatter msgs into acc2
    gemm_mma_kernel<1, true><<<dim3(5, mblocks), 256>>>(acc1, ACC_COLS, B2h, B2l, acc2, msg2);
    scatter_kernel<<<sblocks, 256>>>(eoff, msg2, acc2);

    // out = sigmoid(relu(acc2))
    sigmoid_kernel<<<(N_NODES * 16 + 255) / 256, 256>>>(acc2, out);
}

// round 9
// speedup vs baseline: 1.6815x; 1.1853x over previous
#include <cuda_runtime.h>
#include <cuda_fp16.h>
#include <cstdint>

#define N_NODES   100000
#define E_PER_REL 150000
#define R_REL     4
#define E_TOTAL   (E_PER_REL * R_REL)
#define MSG_COLS  256
#define ACC_COLS  64

// ---------------------------------------------------------------------------
// Device globals (no runtime allocation allowed)
// ---------------------------------------------------------------------------
__device__ __align__(128) float  g_acc1[(size_t)N_NODES * ACC_COLS];  // 25.6 MB
__device__ __align__(128) float  g_acc2[(size_t)N_NODES * ACC_COLS];  // 25.6 MB
__device__ __align__(128) __half g_msg1[(size_t)N_NODES * MSG_COLS];  // 51.2 MB
__device__ __align__(128) __half g_msg2[(size_t)N_NODES * MSG_COLS];  // 51.2 MB
// Pre-swizzled fp16 weight tiles: [cb*CHUNKS+ch] tiles of 64n x 64k (8192 B)
__device__ __align__(256) __half g_B1h[5 * 2 * 64 * 64];
__device__ __align__(256) __half g_B1l[5 * 2 * 64 * 64];
__device__ __align__(256) __half g_B2h[5 * 1 * 64 * 64];
__device__ __align__(256) __half g_B2l[5 * 1 * 64 * 64];
__device__ int2 g_eoff[E_TOTAL];   // {src half-offset into msg, dst float-offset into acc}
__device__ int g_idx_is64;

// XOR swizzle on 16B granules within a 128B row: byte offset for (row, k)
__device__ __forceinline__ uint32_t swz(uint32_t row, uint32_t k) {
    uint32_t g = k >> 3;
    return row * 128u + (((g ^ (row & 7u)) << 4) | ((k & 7u) << 1));
}

// ---------------------------------------------------------------------------
__global__ void sniff_kernel(const unsigned int* __restrict__ idx) {
    __shared__ int nz;
    if (threadIdx.x == 0) nz = 0;
    __syncthreads();
    for (int i = threadIdx.x; i < 4096; i += blockDim.x)
        if (idx[2 * i + 1] != 0u) nz = 1;
    __syncthreads();
    if (threadIdx.x == 0) g_idx_is64 = (nz == 0) ? 1 : 0;
}

__global__ void prep_idx_kernel(const void* __restrict__ src_v,
                                const void* __restrict__ dst_v,
                                int2* __restrict__ eoff) {
    int e = blockIdx.x * blockDim.x + threadIdx.x;
    if (e >= E_TOTAL) return;
    int r = e / E_PER_REL;
    int s, d;
    if (g_idx_is64) {
        s = (int)((const long long*)src_v)[e];
        d = (int)((const long long*)dst_v)[e];
    } else {
        s = ((const int*)src_v)[e];
        d = ((const int*)dst_v)[e];
    }
    eoff[e] = make_int2(s * MSG_COLS + r * 64, d * ACC_COLS);
}

// ---------------------------------------------------------------------------
// Weight prep: combined signed weights -> swizzled fp16 hi/lo tiles.
// Column c: 0..63 = Wself; 64.. = sign_r * Wrel.
// ---------------------------------------------------------------------------
__global__ void prep_w_kernel(const float* __restrict__ Wrel,
                              const float* __restrict__ Wself,
                              __half* __restrict__ Bh,
                              __half* __restrict__ Bl,
                              int din, int chunks) {
    int idx = blockIdx.x * blockDim.x + threadIdx.x;   // c * din + d
    if (idx >= 320 * din) return;
    int c = idx / din;
    int d = idx - c * din;
    float v;
    if (c < 64) {
        v = Wself[d * 64 + c];
    } else {
        int r = (c - 64) >> 6;
        int o = (c - 64) & 63;
        v = Wrel[((size_t)r * din + d) * 64 + o];
        if (r == 3) v = -v;   // SUBTRACT_REL = 3
    }
    __half hi = __float2half_rn(v);
    __half lo = __float2half_rn(v - __half2float(hi));
    int cb = c >> 6, n = c & 63;
    int ch = d >> 6, k = d & 63;
    size_t tile = (size_t)(cb * chunks + ch) * 8192;   // bytes
    uint32_t off = swz((uint32_t)n, (uint32_t)k);
    *(__half*)((char*)Bh + tile + off) = hi;
    *(__half*)((char*)Bl + tile + off) = lo;
}

// ---------------------------------------------------------------------------
__device__ __forceinline__ void mma16816(float* c, const uint32_t* a, uint32_t b0, uint32_t b1) {
    asm volatile("mma.sync.aligned.m16n8k16.row.col.f32.f16.f16.f32 "
                 "{%0,%1,%2,%3}, {%4,%5,%6,%7}, {%8,%9}, {%0,%1,%2,%3};"
                 : "+f"(c[0]), "+f"(c[1]), "+f"(c[2]), "+f"(c[3])
                 : "r"(a[0]), "r"(a[1]), "r"(a[2]), "r"(a[3]), "r"(b0), "r"(b1));
}
__device__ __forceinline__ void ldsm4(uint32_t* r, uint32_t addr) {
    asm volatile("ldmatrix.sync.aligned.m8n8.x4.shared.b16 {%0,%1,%2,%3}, [%4];"
                 : "=r"(r[0]), "=r"(r[1]), "=r"(r[2]), "=r"(r[3]) : "r"(addr));
}

// ---------------------------------------------------------------------------
// Tensor-core GEMM. CTA = 128m x 64n; cb = blockIdx.x (0..4), mblock = blockIdx.y.
// cb 0 (self path -> f32 acc): 3-MMA fp16 hi/lo split (error ~2^-22).
// cb 1..4 (messages -> fp16 msg): single fp16 MMA (error ~ fp16 storage quant).
// 8 warps as 4(m) x 2(n); warp tile 32m x 32n.
// ---------------------------------------------------------------------------
#define STG_STRIDE 72   // halves per staged row (64 + 8 pad -> 144 B)

template <int CHUNKS, bool RELU>
__global__ void __launch_bounds__(256, 2) gemm_mma_kernel(const float* __restrict__ A, int lda,
                                                          const __half* __restrict__ Bh,
                                                          const __half* __restrict__ Bl,
                                                          float* __restrict__ Cacc,
                                                          __half* __restrict__ Cmsg) {
    __shared__ __align__(16) char S[49152];
    __half* Ah  = (__half*)(S);             // 16 KB
    __half* Al  = (__half*)(S + 16384);     // 16 KB (unused for cb>=1)
    __half* Bhs = (__half*)(S + 32768);     // 8 KB
    __half* Bls = (__half*)(S + 40960);     // 8 KB (unused for cb>=1)
    __half* stage = (__half*)S;             // reused post-compute (18.4 KB)

    const int tid  = threadIdx.x;
    const int wid  = tid >> 5;
    const int lane = tid & 31;
    const int cb   = blockIdx.x;      // column block (0..4)
    const bool full = (cb == 0);      // hi/lo split path
    const int m0   = blockIdx.y * 128;
    const int wm   = wid >> 1;        // 0..3 (m quarter)
    const int wn   = wid & 1;         // 0..1 (n half)

    const uint32_t ah_u = (uint32_t)__cvta_generic_to_shared(Ah);
    const uint32_t al_u = (uint32_t)__cvta_generic_to_shared(Al);
    const uint32_t bh_u = (uint32_t)__cvta_generic_to_shared(Bhs);
    const uint32_t bl_u = (uint32_t)__cvta_generic_to_shared(Bls);

    // ldmatrix lane geometry
    const int tq = lane >> 3;
    const int lr = lane & 7;
    const int a_lrow = lr + (tq & 1) * 8;
    const int a_gad  = (tq >> 1);
    const int b_lr   = lr + (tq >> 1) * 8;
    const int b_gad  = (tq & 1);

    float acc[2][4][4];
#pragma unroll
    for (int mt = 0; mt < 2; mt++)
#pragma unroll
        for (int j = 0; j < 4; j++)
#pragma unroll
            for (int q = 0; q < 4; q++) acc[mt][j][q] = 0.f;

    for (int ch = 0; ch < CHUNKS; ch++) {
        // ---- Copy pre-swizzled B tile (hi always, lo only for cb=0)
        {
            size_t tile = (size_t)(cb * CHUNKS + ch) * 8192;
            const uint4* sh = (const uint4*)((const char*)Bh + tile);
            uint4* dh = (uint4*)Bhs;
            dh[tid] = sh[tid]; dh[tid + 256] = sh[tid + 256];
            if (full) {
                const uint4* sl = (const uint4*)((const char*)Bl + tile);
                uint4* dl = (uint4*)Bls;
                dl[tid] = sl[tid]; dl[tid + 256] = sl[tid + 256];
            }
        }
        // ---- Load + convert A tile [128m x 64k] f32 -> fp16 (hi, and lo if full)
#pragma unroll
        for (int i = 0; i < 4; i++) {
            int gran = i * 256 + tid;       // 1024 granules of 8 k-values
            int m = gran >> 3;
            int g = gran & 7;
            int gr = m0 + m;
            float4 v0 = make_float4(0.f, 0.f, 0.f, 0.f), v1 = v0;
            if (gr < N_NODES) {
                const float* ap = &A[(size_t)gr * lda + ch * 64 + g * 8];
                v0 = *(const float4*)ap;
                v1 = *(const float4*)(ap + 4);
                if (RELU) {
                    v0.x = fmaxf(v0.x, 0.f); v0.y = fmaxf(v0.y, 0.f);
                    v0.z = fmaxf(v0.z, 0.f); v0.w = fmaxf(v0.w, 0.f);
                    v1.x = fmaxf(v1.x, 0.f); v1.y = fmaxf(v1.y, 0.f);
                    v1.z = fmaxf(v1.z, 0.f); v1.w = fmaxf(v1.w, 0.f);
                }
            }
            float f[8] = {v0.x, v0.y, v0.z, v0.w, v1.x, v1.y, v1.z, v1.w};
            __half h[8];
#pragma unroll
            for (int j = 0; j < 8; j++) h[j] = __float2half_rn(f[j]);
            uint32_t off = swz((uint32_t)m, (uint32_t)(g * 8));
            *(uint4*)((char*)Ah + off) = *(const uint4*)h;
            if (full) {
                __half l[8];
#pragma unroll
                for (int j = 0; j < 8; j++)
                    l[j] = __float2half_rn(f[j] - __half2float(h[j]));
                *(uint4*)((char*)Al + off) = *(const uint4*)l;
            }
        }
        __syncthreads();

        // ---- Compute: 4 k-steps of 16
#pragma unroll
        for (int ks = 0; ks < 4; ks++) {
            uint32_t afh[2][4], bfh[2][4];
#pragma unroll
            for (int mt = 0; mt < 2; mt++) {
                int arow = wm * 32 + mt * 16 + a_lrow;
                uint32_t a_off = arow * 128u +
                                 (((uint32_t)((ks * 2 + a_gad) ^ (arow & 7))) << 4);
                ldsm4(afh[mt], ah_u + a_off);
            }
#pragma unroll
            for (int bt = 0; bt < 2; bt++) {
                int brow = wn * 32 + bt * 16 + b_lr;
                uint32_t b_off = brow * 128u +
                                 (((uint32_t)((ks * 2 + b_gad) ^ (brow & 7))) << 4);
                ldsm4(bfh[bt], bh_u + b_off);
            }
#pragma unroll
            for (int mt = 0; mt < 2; mt++)
#pragma unroll
                for (int bt = 0; bt < 2; bt++) {
                    mma16816(acc[mt][bt * 2 + 0], afh[mt], bfh[bt][0], bfh[bt][1]);
                    mma16816(acc[mt][bt * 2 + 1], afh[mt], bfh[bt][2], bfh[bt][3]);
                }
            if (full) {
                uint32_t afl[2][4], bfl[2][4];
#pragma unroll
                for (int mt = 0; mt < 2; mt++) {
                    int arow = wm * 32 + mt * 16 + a_lrow;
                    uint32_t a_off = arow * 128u +
                                     (((uint32_t)((ks * 2 + a_gad) ^ (arow & 7))) << 4);
                    ldsm4(afl[mt], al_u + a_off);
                }
#pragma unroll
                for (int bt = 0; bt < 2; bt++) {
                    int brow = wn * 32 + bt * 16 + b_lr;
                    uint32_t b_off = brow * 128u +
                                     (((uint32_t)((ks * 2 + b_gad) ^ (brow & 7))) << 4);
                    ldsm4(bfl[bt], bl_u + b_off);
                }
#pragma unroll
                for (int mt = 0; mt < 2; mt++)
#pragma unroll
                    for (int bt = 0; bt < 2; bt++) {
                        mma16816(acc[mt][bt * 2 + 0], afh[mt], bfl[bt][0], bfl[bt][1]);
                        mma16816(acc[mt][bt * 2 + 0], afl[mt], bfh[bt][0], bfh[bt][1]);
                        mma16816(acc[mt][bt * 2 + 1], afh[mt], bfl[bt][2], bfl[bt][3]);
                        mma16816(acc[mt][bt * 2 + 1], afl[mt], bfh[bt][2], bfh[bt][3]);
                    }
            }
        }
        __syncthreads();
    }

    const int ccol = (lane & 3) * 2;
    if (full) {
        // ---- f32 epilogue into acc[N,64]
#pragma unroll
        for (int mt = 0; mt < 2; mt++) {
            int gr0 = m0 + wm * 32 + mt * 16 + (lane >> 2);
            int gr1 = gr0 + 8;
#pragma unroll
            for (int j = 0; j < 4; j++) {
                int gc = wn * 32 + j * 8 + ccol;
                if (gr0 < N_NODES)
                    *(float2*)&Cacc[(size_t)gr0 * ACC_COLS + gc] =
                        make_float2(acc[mt][j][0], acc[mt][j][1]);
                if (gr1 < N_NODES)
                    *(float2*)&Cacc[(size_t)gr1 * ACC_COLS + gc] =
                        make_float2(acc[mt][j][2], acc[mt][j][3]);
            }
        }
    } else {
        // ---- fp16 epilogue into msg[N,256], staged for coalesced stores
#pragma unroll
        for (int mt = 0; mt < 2; mt++) {
            int lrow0 = wm * 32 + mt * 16 + (lane >> 2);
#pragma unroll
            for (int j = 0; j < 4; j++) {
                int lc = wn * 32 + j * 8 + ccol;
                *(__half2*)&stage[lrow0 * STG_STRIDE + lc] =
                    __floats2half2_rn(acc[mt][j][0], acc[mt][j][1]);
                *(__half2*)&stage[(lrow0 + 8) * STG_STRIDE + lc] =
                    __floats2half2_rn(acc[mt][j][2], acc[mt][j][3]);
            }
        }
        __syncthreads();
        const int mbase = (cb - 1) * 64;
#pragma unroll
        for (int i = 0; i < 4; i++) {
            int chunk = i * 256 + tid;      // 1024 chunks of 16 B
            int row = chunk >> 3;
            int cc  = chunk & 7;
            int gr = m0 + row;
            if (gr < N_NODES) {
                uint4 v = *(const uint4*)&stage[row * STG_STRIDE + cc * 8];
                *(uint4*)&Cmsg[(size_t)gr * MSG_COLS + mbase + cc * 8] = v;
            }
        }
    }
}

// ---------------------------------------------------------------------------
// Scatter: acc[dst][0:64] += f32(msg[src][r*64:r*64+64])  (signs pre-folded)
// 8 threads/edge; 16B uint4 gather of 8 halves; 2 vector REDs per thread.
// ---------------------------------------------------------------------------
__global__ void __launch_bounds__(256) scatter_kernel(const int2* __restrict__ eoff,
                                                      const __half* __restrict__ msg,
                                                      float* __restrict__ acc) {
    int gid  = blockIdx.x * blockDim.x + threadIdx.x;
    int edge = gid >> 3;
    if (edge >= E_TOTAL) return;
    int sub = gid & 7;

    int2 eo = __ldg(&eoff[edge]);   // 8 lanes load the same 8B -> L1 broadcast

    const __half2* mp = (const __half2*)&msg[(size_t)eo.x + sub * 8];
    float2 f0 = __half22float2(mp[0]);
    float2 f1 = __half22float2(mp[1]);
    float2 f2 = __half22float2(mp[2]);
    float2 f3 = __half22float2(mp[3]);

    float* p = &acc[(size_t)eo.y + sub * 8];
    asm volatile("red.global.add.v4.f32 [%0], {%1,%2,%3,%4};"
                 :: "l"(p), "f"(f0.x), "f"(f0.y), "f"(f1.x), "f"(f1.y) : "memory");
    asm volatile("red.global.add.v4.f32 [%0], {%1,%2,%3,%4};"
                 :: "l"(p + 4), "f"(f2.x), "f"(f2.y), "f"(f3.x), "f"(f3.y) : "memory");
}

// ---------------------------------------------------------------------------
// out = sigmoid(relu(acc2))  — fully contiguous
// ---------------------------------------------------------------------------
__global__ void __launch_bounds__(256) sigmoid_kernel(const float* __restrict__ acc,
                                                      float* __restrict__ out) {
    int idx = blockIdx.x * blockDim.x + threadIdx.x;
    if (idx >= N_NODES * 16) return;
    float4 v = *(const float4*)&acc[(size_t)idx * 4];
    v.x = 1.f / (1.f + __expf(-fmaxf(v.x, 0.f)));
    v.y = 1.f / (1.f + __expf(-fmaxf(v.y, 0.f)));
    v.z = 1.f / (1.f + __expf(-fmaxf(v.z, 0.f)));
    v.w = 1.f / (1.f + __expf(-fmaxf(v.w, 0.f)));
    *(float4*)&out[(size_t)idx * 4] = v;
}

// ---------------------------------------------------------------------------
extern "C" void kernel_launch(void* const* d_in, const int* in_sizes, int n_in,
                              void* d_out, int out_size) {
    const float* node_emb = (const float*)d_in[0];
    const void*  src      = d_in[1];
    const void*  dst      = d_in[2];
    const float* W1       = (const float*)d_in[3];
    const float* Wself1   = (const float*)d_in[4];
    const float* W2       = (const float*)d_in[5];
    const float* Wself2   = (const float*)d_in[6];
    float*       out      = (float*)d_out;

    float *acc1, *acc2;
    __half *msg1, *msg2;
    __half *B1h, *B1l, *B2h, *B2l;
    int2* eoff;
    cudaGetSymbolAddress((void**)&acc1, g_acc1);
    cudaGetSymbolAddress((void**)&acc2, g_acc2);
    cudaGetSymbolAddress((void**)&msg1, g_msg1);
    cudaGetSymbolAddress((void**)&msg2, g_msg2);
    cudaGetSymbolAddress((void**)&B1h, g_B1h);
    cudaGetSymbolAddress((void**)&B1l, g_B1l);
    cudaGetSymbolAddress((void**)&B2h, g_B2h);
    cudaGetSymbolAddress((void**)&B2l, g_B2l);
    cudaGetSymbolAddress((void**)&eoff, g_eoff);

    sniff_kernel<<<1, 256>>>((const unsigned int*)src);
    prep_idx_kernel<<<(E_TOTAL + 255) / 256, 256>>>(src, dst, eoff);
    prep_w_kernel<<<(320 * 128 + 255) / 256, 256>>>(W1, Wself1, B1h, B1l, 128, 2);
    prep_w_kernel<<<(320 * 64 + 255) / 256, 256>>>(W2, Wself2, B2h, B2l, 64, 1);

    const int mblocks = (N_NODES + 127) / 128;   // 782
    const int sblocks = (E_TOTAL * 8 + 255) / 256;

    // Layer 1: acc1/msg1 = node_emb @ Wc1; scatter msgs into acc1
    gemm_mma_kernel<2, false><<<dim3(5, mblocks), 256>>>(node_emb, 128, B1h, B1l, acc1, msg1);
    scatter_kernel<<<sblocks, 256>>>(eoff, msg1, acc1);

    // Layer 2: acc2/msg2 = relu(acc1) @ Wc2; scatter msgs into acc2
    gemm_mma_kernel<1, true><<<dim3(5, mblocks), 256>>>(acc1, ACC_COLS, B2h, B2l, acc2, msg2);
    scatter_kernel<<<sblocks, 256>>>(eoff, msg2, acc2);

    // out = sigmoid(relu(acc2))
    sigmoid_kernel<<<(N_NODES * 16 + 255) / 256, 256>>>(acc2, out);
}

// round 10
// speedup vs baseline: 1.7854x; 1.0618x over previous
#include <cuda_runtime.h>
#include <cuda_fp16.h>
#include <cstdint>

#define N_NODES   100000
#define E_PER_REL 150000
#define R_REL     4
#define E_TOTAL   (E_PER_REL * R_REL)
#define MSG_COLS  256
#define ACC_COLS  64

// ---------------------------------------------------------------------------
// Device globals (no runtime allocation allowed)
// ---------------------------------------------------------------------------
__device__ __align__(128) float  g_acc1[(size_t)N_NODES * ACC_COLS];  // 25.6 MB
__device__ __align__(128) float  g_acc2[(size_t)N_NODES * ACC_COLS];  // 25.6 MB
__device__ __align__(128) __half g_msg1[(size_t)N_NODES * MSG_COLS];  // 51.2 MB
__device__ __align__(128) __half g_msg2[(size_t)N_NODES * MSG_COLS];  // 51.2 MB
// Pre-swizzled fp16 weight tiles: [cb*CHUNKS+ch] tiles of 64n x 64k (8192 B)
__device__ __align__(256) __half g_B1[5 * 2 * 64 * 64];
__device__ __align__(256) __half g_B2[5 * 1 * 64 * 64];
__device__ __align__(16) int2 g_eoff[E_TOTAL];  // {src half-off into msg, dst f32-off into acc}
__device__ int g_idx_is64;

// XOR swizzle on 16B granules within a 128B row: byte offset for (row, k)
__device__ __forceinline__ uint32_t swz(uint32_t row, uint32_t k) {
    uint32_t g = k >> 3;
    return row * 128u + (((g ^ (row & 7u)) << 4) | ((k & 7u) << 1));
}

// ---------------------------------------------------------------------------
__global__ void sniff_kernel(const unsigned int* __restrict__ idx) {
    __shared__ int nz;
    if (threadIdx.x == 0) nz = 0;
    __syncthreads();
    for (int i = threadIdx.x; i < 4096; i += blockDim.x)
        if (idx[2 * i + 1] != 0u) nz = 1;
    __syncthreads();
    if (threadIdx.x == 0) g_idx_is64 = (nz == 0) ? 1 : 0;
}

__global__ void prep_idx_kernel(const void* __restrict__ src_v,
                                const void* __restrict__ dst_v,
                                int2* __restrict__ eoff) {
    int e = blockIdx.x * blockDim.x + threadIdx.x;
    if (e >= E_TOTAL) return;
    int r = e / E_PER_REL;
    int s, d;
    if (g_idx_is64) {
        s = (int)((const long long*)src_v)[e];
        d = (int)((const long long*)dst_v)[e];
    } else {
        s = ((const int*)src_v)[e];
        d = ((const int*)dst_v)[e];
    }
    eoff[e] = make_int2(s * MSG_COLS + r * 64, d * ACC_COLS);
}

// ---------------------------------------------------------------------------
// Weight prep (both layers, one launch): combined signed weights -> swizzled
// fp16 tiles. Column c: 0..63 = Wself; 64.. = sign_r * Wrel (r=3 negated).
// ---------------------------------------------------------------------------
__device__ __forceinline__ void prep_one(const float* Wrel, const float* Wself,
                                         __half* B, int din, int chunks, int i) {
    int c = i / din;
    int d = i - c * din;
    float v;
    if (c < 64) {
        v = Wself[d * 64 + c];
    } else {
        int r = (c - 64) >> 6;
        int o = (c - 64) & 63;
        v = Wrel[((size_t)r * din + d) * 64 + o];
        if (r == 3) v = -v;   // SUBTRACT_REL = 3
    }
    int cb = c >> 6, n = c & 63;
    int ch = d >> 6, k = d & 63;
    size_t tile = (size_t)(cb * chunks + ch) * 8192;   // bytes
    *(__half*)((char*)B + tile + swz((uint32_t)n, (uint32_t)k)) = __float2half_rn(v);
}

__global__ void prep_w_kernel(const float* __restrict__ W1, const float* __restrict__ Ws1,
                              const float* __restrict__ W2, const float* __restrict__ Ws2,
                              __half* __restrict__ B1, __half* __restrict__ B2) {
    int idx = blockIdx.x * blockDim.x + threadIdx.x;
    if (idx < 320 * 128) {
        prep_one(W1, Ws1, B1, 128, 2, idx);
    } else if (idx < 320 * 128 + 320 * 64) {
        prep_one(W2, Ws2, B2, 64, 1, idx - 320 * 128);
    }
}

// ---------------------------------------------------------------------------
__device__ __forceinline__ void mma16816(float* c, const uint32_t* a, uint32_t b0, uint32_t b1) {
    asm volatile("mma.sync.aligned.m16n8k16.row.col.f32.f16.f16.f32 "
                 "{%0,%1,%2,%3}, {%4,%5,%6,%7}, {%8,%9}, {%0,%1,%2,%3};"
                 : "+f"(c[0]), "+f"(c[1]), "+f"(c[2]), "+f"(c[3])
                 : "r"(a[0]), "r"(a[1]), "r"(a[2]), "r"(a[3]), "r"(b0), "r"(b1));
}
__device__ __forceinline__ void ldsm4(uint32_t* r, uint32_t addr) {
    asm volatile("ldmatrix.sync.aligned.m8n8.x4.shared.b16 {%0,%1,%2,%3}, [%4];"
                 : "=r"(r[0]), "=r"(r[1]), "=r"(r[2]), "=r"(r[3]) : "r"(addr));
}

// ---------------------------------------------------------------------------
// Tensor-core GEMM. CTA = 128m x 64n; cb = blockIdx.x (0..4), mblock = blockIdx.y.
// Single fp16 MMA (error budget analysis: self-path fp16 quant adds ~3e-4).
// cb 0 -> f32 acc[N,64]; cb 1..4 -> fp16 msg[N,256] (smem-staged stores).
// 8 warps as 4(m) x 2(n); warp tile 32m x 32n.
// ---------------------------------------------------------------------------
#define STG_STRIDE 72   // halves per staged row (64 + 8 pad -> 144 B)

template <int CHUNKS, bool RELU>
__global__ void __launch_bounds__(256, 3) gemm_mma_kernel(const float* __restrict__ A, int lda,
                                                          const __half* __restrict__ B,
                                                          float* __restrict__ Cacc,
                                                          __half* __restrict__ Cmsg) {
    __shared__ __align__(16) char S[24576];
    __half* Ah  = (__half*)(S);             // 16 KB
    __half* Bhs = (__half*)(S + 16384);     // 8 KB
    __half* stage = (__half*)S;             // reused post-compute (18.4 KB)

    const int tid  = threadIdx.x;
    const int wid  = tid >> 5;
    const int lane = tid & 31;
    const int cb   = blockIdx.x;      // column block (0..4)
    const int m0   = blockIdx.y * 128;
    const int wm   = wid >> 1;        // 0..3 (m quarter)
    const int wn   = wid & 1;         // 0..1 (n half)

    const uint32_t ah_u = (uint32_t)__cvta_generic_to_shared(Ah);
    const uint32_t bh_u = (uint32_t)__cvta_generic_to_shared(Bhs);

    // ldmatrix lane geometry
    const int tq = lane >> 3;
    const int lr = lane & 7;
    const int a_lrow = lr + (tq & 1) * 8;
    const int a_gad  = (tq >> 1);
    const int b_lr   = lr + (tq >> 1) * 8;
    const int b_gad  = (tq & 1);

    float acc[2][4][4];
#pragma unroll
    for (int mt = 0; mt < 2; mt++)
#pragma unroll
        for (int j = 0; j < 4; j++)
#pragma unroll
            for (int q = 0; q < 4; q++) acc[mt][j][q] = 0.f;

    for (int ch = 0; ch < CHUNKS; ch++) {
        // ---- Copy pre-swizzled B tile (8 KB)
        {
            size_t tile = (size_t)(cb * CHUNKS + ch) * 8192;
            const uint4* sh = (const uint4*)((const char*)B + tile);
            uint4* dh = (uint4*)Bhs;
            dh[tid] = sh[tid]; dh[tid + 256] = sh[tid + 256];
        }
        // ---- Load + convert A tile [128m x 64k] f32 -> fp16, swizzled
#pragma unroll
        for (int i = 0; i < 4; i++) {
            int gran = i * 256 + tid;       // 1024 granules of 8 k-values
            int m = gran >> 3;
            int g = gran & 7;
            int gr = m0 + m;
            float4 v0 = make_float4(0.f, 0.f, 0.f, 0.f), v1 = v0;
            if (gr < N_NODES) {
                const float* ap = &A[(size_t)gr * lda + ch * 64 + g * 8];
                v0 = *(const float4*)ap;
                v1 = *(const float4*)(ap + 4);
                if (RELU) {
                    v0.x = fmaxf(v0.x, 0.f); v0.y = fmaxf(v0.y, 0.f);
                    v0.z = fmaxf(v0.z, 0.f); v0.w = fmaxf(v0.w, 0.f);
                    v1.x = fmaxf(v1.x, 0.f); v1.y = fmaxf(v1.y, 0.f);
                    v1.z = fmaxf(v1.z, 0.f); v1.w = fmaxf(v1.w, 0.f);
                }
            }
            __half h[8];
            h[0] = __float2half_rn(v0.x); h[1] = __float2half_rn(v0.y);
            h[2] = __float2half_rn(v0.z); h[3] = __float2half_rn(v0.w);
            h[4] = __float2half_rn(v1.x); h[5] = __float2half_rn(v1.y);
            h[6] = __float2half_rn(v1.z); h[7] = __float2half_rn(v1.w);
            uint32_t off = swz((uint32_t)m, (uint32_t)(g * 8));
            *(uint4*)((char*)Ah + off) = *(const uint4*)h;
        }
        __syncthreads();

        // ---- Compute: 4 k-steps of 16
#pragma unroll
        for (int ks = 0; ks < 4; ks++) {
            uint32_t afh[2][4], bfh[2][4];
#pragma unroll
            for (int mt = 0; mt < 2; mt++) {
                int arow = wm * 32 + mt * 16 + a_lrow;
                uint32_t a_off = arow * 128u +
                                 (((uint32_t)((ks * 2 + a_gad) ^ (arow & 7))) << 4);
                ldsm4(afh[mt], ah_u + a_off);
            }
#pragma unroll
            for (int bt = 0; bt < 2; bt++) {
                int brow = wn * 32 + bt * 16 + b_lr;
                uint32_t b_off = brow * 128u +
                                 (((uint32_t)((ks * 2 + b_gad) ^ (brow & 7))) << 4);
                ldsm4(bfh[bt], bh_u + b_off);
            }
#pragma unroll
            for (int mt = 0; mt < 2; mt++)
#pragma unroll
                for (int bt = 0; bt < 2; bt++) {
                    mma16816(acc[mt][bt * 2 + 0], afh[mt], bfh[bt][0], bfh[bt][1]);
                    mma16816(acc[mt][bt * 2 + 1], afh[mt], bfh[bt][2], bfh[bt][3]);
                }
        }
        __syncthreads();
    }

    const int ccol = (lane & 3) * 2;
    if (cb == 0) {
        // ---- f32 epilogue into acc[N,64]
#pragma unroll
        for (int mt = 0; mt < 2; mt++) {
            int gr0 = m0 + wm * 32 + mt * 16 + (lane >> 2);
            int gr1 = gr0 + 8;
#pragma unroll
            for (int j = 0; j < 4; j++) {
                int gc = wn * 32 + j * 8 + ccol;
                if (gr0 < N_NODES)
                    *(float2*)&Cacc[(size_t)gr0 * ACC_COLS + gc] =
                        make_float2(acc[mt][j][0], acc[mt][j][1]);
                if (gr1 < N_NODES)
                    *(float2*)&Cacc[(size_t)gr1 * ACC_COLS + gc] =
                        make_float2(acc[mt][j][2], acc[mt][j][3]);
            }
        }
    } else {
        // ---- fp16 epilogue into msg[N,256], staged for coalesced stores
#pragma unroll
        for (int mt = 0; mt < 2; mt++) {
            int lrow0 = wm * 32 + mt * 16 + (lane >> 2);
#pragma unroll
            for (int j = 0; j < 4; j++) {
                int lc = wn * 32 + j * 8 + ccol;
                *(__half2*)&stage[lrow0 * STG_STRIDE + lc] =
                    __floats2half2_rn(acc[mt][j][0], acc[mt][j][1]);
                *(__half2*)&stage[(lrow0 + 8) * STG_STRIDE + lc] =
                    __floats2half2_rn(acc[mt][j][2], acc[mt][j][3]);
            }
        }
        __syncthreads();
        const int mbase = (cb - 1) * 64;
#pragma unroll
        for (int i = 0; i < 4; i++) {
            int chunk = i * 256 + tid;      // 1024 chunks of 16 B
            int row = chunk >> 3;
            int cc  = chunk & 7;
            int gr = m0 + row;
            if (gr < N_NODES) {
                uint4 v = *(const uint4*)&stage[row * STG_STRIDE + cc * 8];
                *(uint4*)&Cmsg[(size_t)gr * MSG_COLS + mbase + cc * 8] = v;
            }
        }
    }
}

// ---------------------------------------------------------------------------
// Scatter: acc[dst][0:64] += f32(msg[src][r*64:r*64+64])  (signs pre-folded)
// 8 threads per EDGE-PAIR; one 16B int4 loads both edges' offsets; two
// independent 16B gathers in flight (MLP=2), then 4 vector REDs.
// ---------------------------------------------------------------------------
__global__ void __launch_bounds__(256) scatter_kernel(const int4* __restrict__ eoff2,
                                                      const __half* __restrict__ msg,
                                                      float* __restrict__ acc) {
    int gid  = blockIdx.x * blockDim.x + threadIdx.x;
    int pair = gid >> 3;
    if (pair >= E_TOTAL / 2) return;
    int sub = gid & 7;

    int4 eo = __ldg(&eoff2[pair]);   // {s0, d0, s1, d1}

    const __half2* mp0 = (const __half2*)&msg[(size_t)eo.x + sub * 8];
    const __half2* mp1 = (const __half2*)&msg[(size_t)eo.z + sub * 8];
    __half2 h0[4], h1[4];
    *(uint4*)h0 = *(const uint4*)mp0;   // both gathers issued before any use
    *(uint4*)h1 = *(const uint4*)mp1;

    float2 a0 = __half22float2(h0[0]), a1 = __half22float2(h0[1]);
    float2 a2 = __half22float2(h0[2]), a3 = __half22float2(h0[3]);
    float* p0 = &acc[(size_t)eo.y + sub * 8];
    asm volatile("red.global.add.v4.f32 [%0], {%1,%2,%3,%4};"
                 :: "l"(p0), "f"(a0.x), "f"(a0.y), "f"(a1.x), "f"(a1.y) : "memory");
    asm volatile("red.global.add.v4.f32 [%0], {%1,%2,%3,%4};"
                 :: "l"(p0 + 4), "f"(a2.x), "f"(a2.y), "f"(a3.x), "f"(a3.y) : "memory");

    float2 b0 = __half22float2(h1[0]), b1 = __half22float2(h1[1]);
    float2 b2 = __half22float2(h1[2]), b3 = __half22float2(h1[3]);
    float* p1 = &acc[(size_t)eo.w + sub * 8];
    asm volatile("red.global.add.v4.f32 [%0], {%1,%2,%3,%4};"
                 :: "l"(p1), "f"(b0.x), "f"(b0.y), "f"(b1.x), "f"(b1.y) : "memory");
    asm volatile("red.global.add.v4.f32 [%0], {%1,%2,%3,%4};"
                 :: "l"(p1 + 4), "f"(b2.x), "f"(b2.y), "f"(b3.x), "f"(b3.y) : "memory");
}

// ---------------------------------------------------------------------------
// out = sigmoid(relu(acc2))  — fully contiguous
// ---------------------------------------------------------------------------
__global__ void __launch_bounds__(256) sigmoid_kernel(const float* __restrict__ acc,
                                                      float* __restrict__ out) {
    int idx = blockIdx.x * blockDim.x + threadIdx.x;
    if (idx >= N_NODES * 16) return;
    float4 v = *(const float4*)&acc[(size_t)idx * 4];
    v.x = 1.f / (1.f + __expf(-fmaxf(v.x, 0.f)));
    v.y = 1.f / (1.f + __expf(-fmaxf(v.y, 0.f)));
    v.z = 1.f / (1.f + __expf(-fmaxf(v.z, 0.f)));
    v.w = 1.f / (1.f + __expf(-fmaxf(v.w, 0.f)));
    *(float4*)&out[(size_t)idx * 4] = v;
}

// ---------------------------------------------------------------------------
extern "C" void kernel_launch(void* const* d_in, const int* in_sizes, int n_in,
                              void* d_out, int out_size) {
    const float* node_emb = (const float*)d_in[0];
    const void*  src      = d_in[1];
    const void*  dst      = d_in[2];
    const float* W1       = (const float*)d_in[3];
    const float* Wself1   = (const float*)d_in[4];
    const float* W2       = (const float*)d_in[5];
    const float* Wself2   = (const float*)d_in[6];
    float*       out      = (float*)d_out;

    float *acc1, *acc2;
    __half *msg1, *msg2, *B1, *B2;
    int2* eoff;
    cudaGetSymbolAddress((void**)&acc1, g_acc1);
    cudaGetSymbolAddress((void**)&acc2, g_acc2);
    cudaGetSymbolAddress((void**)&msg1, g_msg1);
    cudaGetSymbolAddress((void**)&msg2, g_msg2);
    cudaGetSymbolAddress((void**)&B1, g_B1);
    cudaGetSymbolAddress((void**)&B2, g_B2);
    cudaGetSymbolAddress((void**)&eoff, g_eoff);

    sniff_kernel<<<1, 256>>>((const unsigned int*)src);
    prep_idx_kernel<<<(E_TOTAL + 255) / 256, 256>>>(src, dst, eoff);
    prep_w_kernel<<<(320 * 128 + 320 * 64 + 255) / 256, 256>>>(W1, Wself1, W2, Wself2, B1, B2);

    const int mblocks = (N_NODES + 127) / 128;             // 782
    const int sblocks = ((E_TOTAL / 2) * 8 + 255) / 256;   // pairs

    // Layer 1: acc1/msg1 = node_emb @ Wc1; scatter msgs into acc1
    gemm_mma_kernel<2, false><<<dim3(5, mblocks), 256>>>(node_emb, 128, B1, acc1, msg1);
    scatter_kernel<<<sblocks, 256>>>((const int4*)eoff, msg1, acc1);

    // Layer 2: acc2/msg2 = relu(acc1) @ Wc2; scatter msgs into acc2
    gemm_mma_kernel<1, true><<<dim3(5, mblocks), 256>>>(acc1, ACC_COLS, B2, acc2, msg2);
    scatter_kernel<<<sblocks, 256>>>((const int4*)eoff, msg2, acc2);

    // out = sigmoid(relu(acc2))
    sigmoid_kernel<<<(N_NODES * 16 + 255) / 256, 256>>>(acc2, out);
}

// round 11
// speedup vs baseline: 2.0272x; 1.1354x over previous
#include <cuda_runtime.h>
#include <cuda_fp16.h>
#include <cstdint>

#define N_NODES   100000
#define E_PER_REL 150000
#define R_REL     4
#define E_TOTAL   (E_PER_REL * R_REL)
#define MSG_COLS  256
#define ACC_COLS  64

// ---------------------------------------------------------------------------
// Device globals (no runtime allocation allowed)
// ---------------------------------------------------------------------------
__device__ __align__(128) float  g_acc1[(size_t)N_NODES * ACC_COLS];  // 25.6 MB
__device__ __align__(128) float  g_acc2[(size_t)N_NODES * ACC_COLS];  // 25.6 MB
__device__ __align__(128) __half g_msg1[(size_t)N_NODES * MSG_COLS];  // 51.2 MB
__device__ __align__(128) __half g_msg2[(size_t)N_NODES * MSG_COLS];  // 51.2 MB
// Pre-swizzled fp16 weight tiles: [cb*CHUNKS+ch] tiles of 64n x 64k (8192 B)
__device__ __align__(256) __half g_B1[5 * 2 * 64 * 64];
__device__ __align__(256) __half g_B2[5 * 1 * 64 * 64];
// dst-sorted edge structures (rebuilt every launch; deterministic work)
__device__ int g_counts[N_NODES];
__device__ int g_starts[N_NODES + 1];
__device__ int g_cursor[N_NODES];
__device__ int g_bsum[128];
__device__ int g_elist[E_TOTAL];    // src msg half-offsets, grouped by dst
__device__ int g_idx_is64;

// XOR swizzle on 16B granules within a 128B row: byte offset for (row, k)
__device__ __forceinline__ uint32_t swz(uint32_t row, uint32_t k) {
    uint32_t g = k >> 3;
    return row * 128u + (((g ^ (row & 7u)) << 4) | ((k & 7u) << 1));
}

// ---------------------------------------------------------------------------
__global__ void sniff_kernel(const unsigned int* __restrict__ idx) {
    __shared__ int nz;
    if (threadIdx.x == 0) nz = 0;
    __syncthreads();
    for (int i = threadIdx.x; i < 4096; i += blockDim.x)
        if (idx[2 * i + 1] != 0u) nz = 1;
    __syncthreads();
    if (threadIdx.x == 0) g_idx_is64 = (nz == 0) ? 1 : 0;
}

__device__ __forceinline__ int load_idx(const void* v, int e) {
    return g_idx_is64 ? (int)((const long long*)v)[e] : ((const int*)v)[e];
}

// ---------------------------------------------------------------------------
// Sort pipeline: count -> scan(98x1024, 2-level) -> fill
// ---------------------------------------------------------------------------
__global__ void count_kernel(const void* __restrict__ dst_v, int* __restrict__ counts) {
    int e = blockIdx.x * blockDim.x + threadIdx.x;
    if (e >= E_TOTAL) return;
    atomicAdd(&counts[load_idx(dst_v, e)], 1);
}

__global__ void scan1_kernel(const int* __restrict__ counts, int* __restrict__ starts,
                             int* __restrict__ bsum) {
    __shared__ int s[256];
    int base = blockIdx.x * 1024 + threadIdx.x * 4;
    int c[4], t = 0;
#pragma unroll
    for (int j = 0; j < 4; j++) {
        c[j] = (base + j < N_NODES) ? counts[base + j] : 0;
        t += c[j];
    }
    s[threadIdx.x] = t;
    __syncthreads();
#pragma unroll
    for (int off = 1; off < 256; off <<= 1) {
        int v = (threadIdx.x >= off) ? s[threadIdx.x - off] : 0;
        __syncthreads();
        s[threadIdx.x] += v;
        __syncthreads();
    }
    int run = s[threadIdx.x] - t;   // exclusive prefix for this thread
#pragma unroll
    for (int j = 0; j < 4; j++) {
        if (base + j < N_NODES) starts[base + j] = run;
        run += c[j];
    }
    if (threadIdx.x == 255) bsum[blockIdx.x] = s[255];
}

__global__ void scan2_kernel(int* __restrict__ bsum, int nb) {
    __shared__ int s[128];
    int t = threadIdx.x;
    int v = (t < nb) ? bsum[t] : 0;
    s[t] = v;
    __syncthreads();
#pragma unroll
    for (int off = 1; off < 128; off <<= 1) {
        int u = (t >= off) ? s[t - off] : 0;
        __syncthreads();
        s[t] += u;
        __syncthreads();
    }
    if (t < nb) bsum[t] = s[t] - v;   // exclusive
}

__global__ void scan3_kernel(int* __restrict__ starts, int* __restrict__ cursor,
                             const int* __restrict__ bsum) {
    int i = blockIdx.x * blockDim.x + threadIdx.x;
    if (i < N_NODES) {
        int v = starts[i] + bsum[i >> 10];
        starts[i] = v;
        cursor[i] = v;
    }
    if (i == N_NODES) starts[N_NODES] = E_TOTAL;
}

__global__ void fill_kernel(const void* __restrict__ src_v, const void* __restrict__ dst_v,
                            int* __restrict__ cursor, int* __restrict__ elist) {
    int e = blockIdx.x * blockDim.x + threadIdx.x;
    if (e >= E_TOTAL) return;
    int r = e / E_PER_REL;
    int s = load_idx(src_v, e);
    int d = load_idx(dst_v, e);
    int pos = atomicAdd(&cursor[d], 1);
    elist[pos] = s * MSG_COLS + r * 64;
}

// ---------------------------------------------------------------------------
// Weight prep (both layers, one launch): combined signed weights -> swizzled
// fp16 tiles. Column c: 0..63 = Wself; 64.. = sign_r * Wrel (r=3 negated).
// ---------------------------------------------------------------------------
__device__ __forceinline__ void prep_one(const float* Wrel, const float* Wself,
                                         __half* B, int din, int chunks, int i) {
    int c = i / din;
    int d = i - c * din;
    float v;
    if (c < 64) {
        v = Wself[d * 64 + c];
    } else {
        int r = (c - 64) >> 6;
        int o = (c - 64) & 63;
        v = Wrel[((size_t)r * din + d) * 64 + o];
        if (r == 3) v = -v;   // SUBTRACT_REL = 3
    }
    int cb = c >> 6, n = c & 63;
    int ch = d >> 6, k = d & 63;
    size_t tile = (size_t)(cb * chunks + ch) * 8192;   // bytes
    *(__half*)((char*)B + tile + swz((uint32_t)n, (uint32_t)k)) = __float2half_rn(v);
}

__global__ void prep_w_kernel(const float* __restrict__ W1, const float* __restrict__ Ws1,
                              const float* __restrict__ W2, const float* __restrict__ Ws2,
                              __half* __restrict__ B1, __half* __restrict__ B2) {
    int idx = blockIdx.x * blockDim.x + threadIdx.x;
    if (idx < 320 * 128) {
        prep_one(W1, Ws1, B1, 128, 2, idx);
    } else if (idx < 320 * 128 + 320 * 64) {
        prep_one(W2, Ws2, B2, 64, 1, idx - 320 * 128);
    }
}

// ---------------------------------------------------------------------------
__device__ __forceinline__ void mma16816(float* c, const uint32_t* a, uint32_t b0, uint32_t b1) {
    asm volatile("mma.sync.aligned.m16n8k16.row.col.f32.f16.f16.f32 "
                 "{%0,%1,%2,%3}, {%4,%5,%6,%7}, {%8,%9}, {%0,%1,%2,%3};"
                 : "+f"(c[0]), "+f"(c[1]), "+f"(c[2]), "+f"(c[3])
                 : "r"(a[0]), "r"(a[1]), "r"(a[2]), "r"(a[3]), "r"(b0), "r"(b1));
}
__device__ __forceinline__ void ldsm4(uint32_t* r, uint32_t addr) {
    asm volatile("ldmatrix.sync.aligned.m8n8.x4.shared.b16 {%0,%1,%2,%3}, [%4];"
                 : "=r"(r[0]), "=r"(r[1]), "=r"(r[2]), "=r"(r[3]) : "r"(addr));
}

// ---------------------------------------------------------------------------
// Tensor-core GEMM (unchanged from round 10). CTA = 128m x 64n; cb = blockIdx.x.
// cb 0 -> f32 acc[N,64]; cb 1..4 -> fp16 msg[N,256] (smem-staged stores).
// ---------------------------------------------------------------------------
#define STG_STRIDE 72   // halves per staged row (64 + 8 pad -> 144 B)

template <int CHUNKS, bool RELU>
__global__ void __launch_bounds__(256, 3) gemm_mma_kernel(const float* __restrict__ A, int lda,
                                                          const __half* __restrict__ B,
                                                          float* __restrict__ Cacc,
                                                          __half* __restrict__ Cmsg) {
    __shared__ __align__(16) char S[24576];
    __half* Ah  = (__half*)(S);             // 16 KB
    __half* Bhs = (__half*)(S + 16384);     // 8 KB
    __half* stage = (__half*)S;             // reused post-compute (18.4 KB)

    const int tid  = threadIdx.x;
    const int wid  = tid >> 5;
    const int lane = tid & 31;
    const int cb   = blockIdx.x;      // column block (0..4)
    const int m0   = blockIdx.y * 128;
    const int wm   = wid >> 1;        // 0..3 (m quarter)
    const int wn   = wid & 1;         // 0..1 (n half)

    const uint32_t ah_u = (uint32_t)__cvta_generic_to_shared(Ah);
    const uint32_t bh_u = (uint32_t)__cvta_generic_to_shared(Bhs);

    const int tq = lane >> 3;
    const int lr = lane & 7;
    const int a_lrow = lr + (tq & 1) * 8;
    const int a_gad  = (tq >> 1);
    const int b_lr   = lr + (tq >> 1) * 8;
    const int b_gad  = (tq & 1);

    float acc[2][4][4];
#pragma unroll
    for (int mt = 0; mt < 2; mt++)
#pragma unroll
        for (int j = 0; j < 4; j++)
#pragma unroll
            for (int q = 0; q < 4; q++) acc[mt][j][q] = 0.f;

    for (int ch = 0; ch < CHUNKS; ch++) {
        {
            size_t tile = (size_t)(cb * CHUNKS + ch) * 8192;
            const uint4* sh = (const uint4*)((const char*)B + tile);
            uint4* dh = (uint4*)Bhs;
            dh[tid] = sh[tid]; dh[tid + 256] = sh[tid + 256];
        }
#pragma unroll
        for (int i = 0; i < 4; i++) {
            int gran = i * 256 + tid;
            int m = gran >> 3;
            int g = gran & 7;
            int gr = m0 + m;
            float4 v0 = make_float4(0.f, 0.f, 0.f, 0.f), v1 = v0;
            if (gr < N_NODES) {
                const float* ap = &A[(size_t)gr * lda + ch * 64 + g * 8];
                v0 = *(const float4*)ap;
                v1 = *(const float4*)(ap + 4);
                if (RELU) {
                    v0.x = fmaxf(v0.x, 0.f); v0.y = fmaxf(v0.y, 0.f);
                    v0.z = fmaxf(v0.z, 0.f); v0.w = fmaxf(v0.w, 0.f);
                    v1.x = fmaxf(v1.x, 0.f); v1.y = fmaxf(v1.y, 0.f);
                    v1.z = fmaxf(v1.z, 0.f); v1.w = fmaxf(v1.w, 0.f);
                }
            }
            __half h[8];
            h[0] = __float2half_rn(v0.x); h[1] = __float2half_rn(v0.y);
            h[2] = __float2half_rn(v0.z); h[3] = __float2half_rn(v0.w);
            h[4] = __float2half_rn(v1.x); h[5] = __float2half_rn(v1.y);
            h[6] = __float2half_rn(v1.z); h[7] = __float2half_rn(v1.w);
            uint32_t off = swz((uint32_t)m, (uint32_t)(g * 8));
            *(uint4*)((char*)Ah + off) = *(const uint4*)h;
        }
        __syncthreads();

#pragma unroll
        for (int ks = 0; ks < 4; ks++) {
            uint32_t afh[2][4], bfh[2][4];
#pragma unroll
            for (int mt = 0; mt < 2; mt++) {
                int arow = wm * 32 + mt * 16 + a_lrow;
                uint32_t a_off = arow * 128u +
                                 (((uint32_t)((ks * 2 + a_gad) ^ (arow & 7))) << 4);
                ldsm4(afh[mt], ah_u + a_off);
            }
#pragma unroll
            for (int bt = 0; bt < 2; bt++) {
                int brow = wn * 32 + bt * 16 + b_lr;
                uint32_t b_off = brow * 128u +
                                 (((uint32_t)((ks * 2 + b_gad) ^ (brow & 7))) << 4);
                ldsm4(bfh[bt], bh_u + b_off);
            }
#pragma unroll
            for (int mt = 0; mt < 2; mt++)
#pragma unroll
                for (int bt = 0; bt < 2; bt++) {
                    mma16816(acc[mt][bt * 2 + 0], afh[mt], bfh[bt][0], bfh[bt][1]);
                    mma16816(acc[mt][bt * 2 + 1], afh[mt], bfh[bt][2], bfh[bt][3]);
                }
        }
        __syncthreads();
    }

    const int ccol = (lane & 3) * 2;
    if (cb == 0) {
#pragma unroll
        for (int mt = 0; mt < 2; mt++) {
            int gr0 = m0 + wm * 32 + mt * 16 + (lane >> 2);
            int gr1 = gr0 + 8;
#pragma unroll
            for (int j = 0; j < 4; j++) {
                int gc = wn * 32 + j * 8 + ccol;
                if (gr0 < N_NODES)
                    *(float2*)&Cacc[(size_t)gr0 * ACC_COLS + gc] =
                        make_float2(acc[mt][j][0], acc[mt][j][1]);
                if (gr1 < N_NODES)
                    *(float2*)&Cacc[(size_t)gr1 * ACC_COLS + gc] =
                        make_float2(acc[mt][j][2], acc[mt][j][3]);
            }
        }
    } else {
#pragma unroll
        for (int mt = 0; mt < 2; mt++) {
            int lrow0 = wm * 32 + mt * 16 + (lane >> 2);
#pragma unroll
            for (int j = 0; j < 4; j++) {
                int lc = wn * 32 + j * 8 + ccol;
                *(__half2*)&stage[lrow0 * STG_STRIDE + lc] =
                    __floats2half2_rn(acc[mt][j][0], acc[mt][j][1]);
                *(__half2*)&stage[(lrow0 + 8) * STG_STRIDE + lc] =
                    __floats2half2_rn(acc[mt][j][2], acc[mt][j][3]);
            }
        }
        __syncthreads();
        const int mbase = (cb - 1) * 64;
#pragma unroll
        for (int i = 0; i < 4; i++) {
            int chunk = i * 256 + tid;
            int row = chunk >> 3;
            int cc  = chunk & 7;
            int gr = m0 + row;
            if (gr < N_NODES) {
                uint4 v = *(const uint4*)&stage[row * STG_STRIDE + cc * 8];
                *(uint4*)&Cmsg[(size_t)gr * MSG_COLS + mbase + cc * 8] = v;
            }
        }
    }
}

// ---------------------------------------------------------------------------
// Aggregate: acc[n] += sum of msg[elist[i]] over n's in-edges. No atomics.
// 8 threads per node; 2-deep unrolled gathers (MLP=2); registers accumulate.
// ---------------------------------------------------------------------------
__device__ __forceinline__ void add8(float4& a0, float4& a1, uint4 g) {
    __half2* h = (__half2*)&g;
    float2 f0 = __half22float2(h[0]), f1 = __half22float2(h[1]);
    float2 f2 = __half22float2(h[2]), f3 = __half22float2(h[3]);
    a0.x += f0.x; a0.y += f0.y; a0.z += f1.x; a0.w += f1.y;
    a1.x += f2.x; a1.y += f2.y; a1.z += f3.x; a1.w += f3.y;
}

__global__ void __launch_bounds__(256) agg_kernel(const int* __restrict__ starts,
                                                  const int* __restrict__ elist,
                                                  const __half* __restrict__ msg,
                                                  float* __restrict__ acc) {
    int gid = blockIdx.x * blockDim.x + threadIdx.x;
    int n   = gid >> 3;
    if (n >= N_NODES) return;
    int sub = gid & 7;

    int beg = __ldg(&starts[n]);
    int end = __ldg(&starts[n + 1]);

    float* ap = &acc[(size_t)n * ACC_COLS + sub * 8];
    float4 a0 = *(const float4*)ap;
    float4 a1 = *(const float4*)(ap + 4);

    int i = beg;
    for (; i + 1 < end; i += 2) {
        int o0 = __ldg(&elist[i]);
        int o1 = __ldg(&elist[i + 1]);
        uint4 g0 = *(const uint4*)&msg[(size_t)o0 + sub * 8];
        uint4 g1 = *(const uint4*)&msg[(size_t)o1 + sub * 8];
        add8(a0, a1, g0);
        add8(a0, a1, g1);
    }
    if (i < end) {
        int o0 = __ldg(&elist[i]);
        uint4 g0 = *(const uint4*)&msg[(size_t)o0 + sub * 8];
        add8(a0, a1, g0);
    }

    *(float4*)ap = a0;
    *(float4*)(ap + 4) = a1;
}

// ---------------------------------------------------------------------------
// out = sigmoid(relu(acc2))  — fully contiguous
// ---------------------------------------------------------------------------
__global__ void __launch_bounds__(256) sigmoid_kernel(const float* __restrict__ acc,
                                                      float* __restrict__ out) {
    int idx = blockIdx.x * blockDim.x + threadIdx.x;
    if (idx >= N_NODES * 16) return;
    float4 v = *(const float4*)&acc[(size_t)idx * 4];
    v.x = 1.f / (1.f + __expf(-fmaxf(v.x, 0.f)));
    v.y = 1.f / (1.f + __expf(-fmaxf(v.y, 0.f)));
    v.z = 1.f / (1.f + __expf(-fmaxf(v.z, 0.f)));
    v.w = 1.f / (1.f + __expf(-fmaxf(v.w, 0.f)));
    *(float4*)&out[(size_t)idx * 4] = v;
}

// ---------------------------------------------------------------------------
extern "C" void kernel_launch(void* const* d_in, const int* in_sizes, int n_in,
                              void* d_out, int out_size) {
    const float* node_emb = (const float*)d_in[0];
    const void*  src      = d_in[1];
    const void*  dst      = d_in[2];
    const float* W1       = (const float*)d_in[3];
    const float* Wself1   = (const float*)d_in[4];
    const float* W2       = (const float*)d_in[5];
    const float* Wself2   = (const float*)d_in[6];
    float*       out      = (float*)d_out;

    float *acc1, *acc2;
    __half *msg1, *msg2, *B1, *B2;
    int *counts, *starts, *cursor, *bsum, *elist;
    cudaGetSymbolAddress((void**)&acc1, g_acc1);
    cudaGetSymbolAddress((void**)&acc2, g_acc2);
    cudaGetSymbolAddress((void**)&msg1, g_msg1);
    cudaGetSymbolAddress((void**)&msg2, g_msg2);
    cudaGetSymbolAddress((void**)&B1, g_B1);
    cudaGetSymbolAddress((void**)&B2, g_B2);
    cudaGetSymbolAddress((void**)&counts, g_counts);
    cudaGetSymbolAddress((void**)&starts, g_starts);
    cudaGetSymbolAddress((void**)&cursor, g_cursor);
    cudaGetSymbolAddress((void**)&bsum, g_bsum);
    cudaGetSymbolAddress((void**)&elist, g_elist);

    const int eblocks = (E_TOTAL + 255) / 256;
    const int nb1024  = (N_NODES + 1023) / 1024;           // 98

    // ---- dtype sniff + dst-sorted edge list (per launch; graph-capturable)
    sniff_kernel<<<1, 256>>>((const unsigned int*)src);
    cudaMemsetAsync(counts, 0, N_NODES * sizeof(int));
    count_kernel<<<eblocks, 256>>>(dst, counts);
    scan1_kernel<<<nb1024, 256>>>(counts, starts, bsum);
    scan2_kernel<<<1, 128>>>(bsum, nb1024);
    scan3_kernel<<<(N_NODES + 256) / 256, 256>>>(starts, cursor, bsum);
    fill_kernel<<<eblocks, 256>>>(src, dst, cursor, elist);

    // ---- weights
    prep_w_kernel<<<(320 * 128 + 320 * 64 + 255) / 256, 256>>>(W1, Wself1, W2, Wself2, B1, B2);

    const int mblocks = (N_NODES + 127) / 128;             // 782
    const int ablocks = (N_NODES * 8 + 255) / 256;         // 3125

    // Layer 1: acc1/msg1 = node_emb @ Wc1; aggregate msgs into acc1
    gemm_mma_kernel<2, false><<<dim3(5, mblocks), 256>>>(node_emb, 128, B1, acc1, msg1);
    agg_kernel<<<ablocks, 256>>>(starts, elist, msg1, acc1);

    // Layer 2: acc2/msg2 = relu(acc1) @ Wc2; aggregate msgs into acc2
    gemm_mma_kernel<1, true><<<dim3(5, mblocks), 256>>>(acc1, ACC_COLS, B2, acc2, msg2);
    agg_kernel<<<ablocks, 256>>>(starts, elist, msg2, acc2);

    // out = sigmoid(relu(acc2))
    sigmoid_kernel<<<(N_NODES * 16 + 255) / 256, 256>>>(acc2, out);
}

// round 12
// speedup vs baseline: 2.2332x; 1.1017x over previous
#include <cuda_runtime.h>
#include <cuda_fp16.h>
#include <cstdint>

#define N_NODES   100000
#define E_PER_REL 150000
#define R_REL     4
#define E_TOTAL   (E_PER_REL * R_REL)
#define MSG_COLS  256
#define ACC_COLS  64

// ---------------------------------------------------------------------------
// Device globals (no runtime allocation allowed)
// ---------------------------------------------------------------------------
__device__ __align__(128) __half g_acc1[(size_t)N_NODES * ACC_COLS];  // 12.8 MB
__device__ __align__(128) __half g_acc2[(size_t)N_NODES * ACC_COLS];  // 12.8 MB
__device__ __align__(128) __half g_msg1[(size_t)N_NODES * MSG_COLS];  // 51.2 MB
__device__ __align__(128) __half g_msg2[(size_t)N_NODES * MSG_COLS];  // 51.2 MB
// Pre-swizzled fp16 weight tiles: [cb*CHUNKS+ch] tiles of 64n x 64k (8192 B)
__device__ __align__(256) __half g_B1[5 * 2 * 64 * 64];
__device__ __align__(256) __half g_B2[5 * 1 * 64 * 64];
// dst-sorted edge structures (rebuilt every launch; deterministic work)
__device__ int g_counts[N_NODES];
__device__ int g_starts[N_NODES + 1];
__device__ int g_cursor[N_NODES];
__device__ int g_bsum[128];
__device__ int g_elist[E_TOTAL];    // src msg half-offsets, grouped by dst
__device__ int g_idx_is64;

// XOR swizzle on 16B granules within a 128B row: byte offset for (row, k)
__device__ __forceinline__ uint32_t swz(uint32_t row, uint32_t k) {
    uint32_t g = k >> 3;
    return row * 128u + (((g ^ (row & 7u)) << 4) | ((k & 7u) << 1));
}

// ---------------------------------------------------------------------------
__global__ void sniff_kernel(const unsigned int* __restrict__ idx) {
    __shared__ int nz;
    if (threadIdx.x == 0) nz = 0;
    __syncthreads();
    for (int i = threadIdx.x; i < 4096; i += blockDim.x)
        if (idx[2 * i + 1] != 0u) nz = 1;
    __syncthreads();
    if (threadIdx.x == 0) g_idx_is64 = (nz == 0) ? 1 : 0;
}

__device__ __forceinline__ int load_idx(const void* v, int e) {
    return g_idx_is64 ? (int)((const long long*)v)[e] : ((const int*)v)[e];
}

// ---------------------------------------------------------------------------
// Sort pipeline: count -> scan(98x1024, 2-level) -> fill
// ---------------------------------------------------------------------------
__global__ void count_kernel(const void* __restrict__ dst_v, int* __restrict__ counts) {
    int e = blockIdx.x * blockDim.x + threadIdx.x;
    if (e >= E_TOTAL) return;
    atomicAdd(&counts[load_idx(dst_v, e)], 1);
}

__global__ void scan1_kernel(const int* __restrict__ counts, int* __restrict__ starts,
                             int* __restrict__ bsum) {
    __shared__ int s[256];
    int base = blockIdx.x * 1024 + threadIdx.x * 4;
    int c[4], t = 0;
#pragma unroll
    for (int j = 0; j < 4; j++) {
        c[j] = (base + j < N_NODES) ? counts[base + j] : 0;
        t += c[j];
    }
    s[threadIdx.x] = t;
    __syncthreads();
#pragma unroll
    for (int off = 1; off < 256; off <<= 1) {
        int v = (threadIdx.x >= off) ? s[threadIdx.x - off] : 0;
        __syncthreads();
        s[threadIdx.x] += v;
        __syncthreads();
    }
    int run = s[threadIdx.x] - t;   // exclusive prefix for this thread
#pragma unroll
    for (int j = 0; j < 4; j++) {
        if (base + j < N_NODES) starts[base + j] = run;
        run += c[j];
    }
    if (threadIdx.x == 255) bsum[blockIdx.x] = s[255];
}

__global__ void scan2_kernel(int* __restrict__ bsum, int nb) {
    __shared__ int s[128];
    int t = threadIdx.x;
    int v = (t < nb) ? bsum[t] : 0;
    s[t] = v;
    __syncthreads();
#pragma unroll
    for (int off = 1; off < 128; off <<= 1) {
        int u = (t >= off) ? s[t - off] : 0;
        __syncthreads();
        s[t] += u;
        __syncthreads();
    }
    if (t < nb) bsum[t] = s[t] - v;   // exclusive
}

__global__ void scan3_kernel(int* __restrict__ starts, int* __restrict__ cursor,
                             const int* __restrict__ bsum) {
    int i = blockIdx.x * blockDim.x + threadIdx.x;
    if (i < N_NODES) {
        int v = starts[i] + bsum[i >> 10];
        starts[i] = v;
        cursor[i] = v;
    }
    if (i == N_NODES) starts[N_NODES] = E_TOTAL;
}

__global__ void fill_kernel(const void* __restrict__ src_v, const void* __restrict__ dst_v,
                            int* __restrict__ cursor, int* __restrict__ elist) {
    int e = blockIdx.x * blockDim.x + threadIdx.x;
    if (e >= E_TOTAL) return;
    int r = e / E_PER_REL;
    int s = load_idx(src_v, e);
    int d = load_idx(dst_v, e);
    int pos = atomicAdd(&cursor[d], 1);
    elist[pos] = s * MSG_COLS + r * 64;
}

// ---------------------------------------------------------------------------
// Weight prep (both layers, one launch): combined signed weights -> swizzled
// fp16 tiles. Column c: 0..63 = Wself; 64.. = sign_r * Wrel (r=3 negated).
// ---------------------------------------------------------------------------
__device__ __forceinline__ void prep_one(const float* Wrel, const float* Wself,
                                         __half* B, int din, int chunks, int i) {
    int c = i / din;
    int d = i - c * din;
    float v;
    if (c < 64) {
        v = Wself[d * 64 + c];
    } else {
        int r = (c - 64) >> 6;
        int o = (c - 64) & 63;
        v = Wrel[((size_t)r * din + d) * 64 + o];
        if (r == 3) v = -v;   // SUBTRACT_REL = 3
    }
    int cb = c >> 6, n = c & 63;
    int ch = d >> 6, k = d & 63;
    size_t tile = (size_t)(cb * chunks + ch) * 8192;   // bytes
    *(__half*)((char*)B + tile + swz((uint32_t)n, (uint32_t)k)) = __float2half_rn(v);
}

__global__ void prep_w_kernel(const float* __restrict__ W1, const float* __restrict__ Ws1,
                              const float* __restrict__ W2, const float* __restrict__ Ws2,
                              __half* __restrict__ B1, __half* __restrict__ B2) {
    int idx = blockIdx.x * blockDim.x + threadIdx.x;
    if (idx < 320 * 128) {
        prep_one(W1, Ws1, B1, 128, 2, idx);
    } else if (idx < 320 * 128 + 320 * 64) {
        prep_one(W2, Ws2, B2, 64, 1, idx - 320 * 128);
    }
}

// ---------------------------------------------------------------------------
__device__ __forceinline__ void mma16816(float* c, const uint32_t* a, uint32_t b0, uint32_t b1) {
    asm volatile("mma.sync.aligned.m16n8k16.row.col.f32.f16.f16.f32 "
                 "{%0,%1,%2,%3}, {%4,%5,%6,%7}, {%8,%9}, {%0,%1,%2,%3};"
                 : "+f"(c[0]), "+f"(c[1]), "+f"(c[2]), "+f"(c[3])
                 : "r"(a[0]), "r"(a[1]), "r"(a[2]), "r"(a[3]), "r"(b0), "r"(b1));
}
__device__ __forceinline__ void ldsm4(uint32_t* r, uint32_t addr) {
    asm volatile("ldmatrix.sync.aligned.m8n8.x4.shared.b16 {%0,%1,%2,%3}, [%4];"
                 : "=r"(r[0]), "=r"(r[1]), "=r"(r[2]), "=r"(r[3]) : "r"(addr));
}

// ---------------------------------------------------------------------------
// Tensor-core GEMM. CTA = 128m x 64n; cb = blockIdx.x (0..4), mblock = blockIdx.y.
// AHALF: A already fp16 (layer 2 reads acc1 directly, no conversion).
// All outputs fp16, staged in smem for coalesced 16B stores:
//   cb 0 -> acc[N,64]; cb 1..4 -> msg[N,256].
// ---------------------------------------------------------------------------
#define STG_STRIDE 72   // halves per staged row (64 + 8 pad -> 144 B)

template <int CHUNKS, bool AHALF>
__global__ void __launch_bounds__(256, 3) gemm_mma_kernel(const void* __restrict__ A, int lda,
                                                          const __half* __restrict__ B,
                                                          __half* __restrict__ Cacc,
                                                          __half* __restrict__ Cmsg) {
    __shared__ __align__(16) char S[24576];
    __half* Ah  = (__half*)(S);             // 16 KB
    __half* Bhs = (__half*)(S + 16384);     // 8 KB
    __half* stage = (__half*)S;             // reused post-compute (18.4 KB)

    const int tid  = threadIdx.x;
    const int wid  = tid >> 5;
    const int lane = tid & 31;
    const int cb   = blockIdx.x;      // column block (0..4)
    const int m0   = blockIdx.y * 128;
    const int wm   = wid >> 1;        // 0..3 (m quarter)
    const int wn   = wid & 1;         // 0..1 (n half)

    const uint32_t ah_u = (uint32_t)__cvta_generic_to_shared(Ah);
    const uint32_t bh_u = (uint32_t)__cvta_generic_to_shared(Bhs);

    const int tq = lane >> 3;
    const int lr = lane & 7;
    const int a_lrow = lr + (tq & 1) * 8;
    const int a_gad  = (tq >> 1);
    const int b_lr   = lr + (tq >> 1) * 8;
    const int b_gad  = (tq & 1);

    float acc[2][4][4];
#pragma unroll
    for (int mt = 0; mt < 2; mt++)
#pragma unroll
        for (int j = 0; j < 4; j++)
#pragma unroll
            for (int q = 0; q < 4; q++) acc[mt][j][q] = 0.f;

    for (int ch = 0; ch < CHUNKS; ch++) {
        {   // copy pre-swizzled B tile (8 KB)
            size_t tile = (size_t)(cb * CHUNKS + ch) * 8192;
            const uint4* sh = (const uint4*)((const char*)B + tile);
            uint4* dh = (uint4*)Bhs;
            dh[tid] = sh[tid]; dh[tid + 256] = sh[tid + 256];
        }
        // ---- A tile [128m x 64k] into swizzled smem
#pragma unroll
        for (int i = 0; i < 4; i++) {
            int gran = i * 256 + tid;       // 1024 granules of 8 k-values
            int m = gran >> 3;
            int g = gran & 7;
            int gr = m0 + m;
            uint32_t off = swz((uint32_t)m, (uint32_t)(g * 8));
            if (AHALF) {
                uint4 v = make_uint4(0u, 0u, 0u, 0u);
                if (gr < N_NODES)
                    v = *(const uint4*)&((const __half*)A)[(size_t)gr * lda + ch * 64 + g * 8];
                *(uint4*)((char*)Ah + off) = v;
            } else {
                float4 v0 = make_float4(0.f, 0.f, 0.f, 0.f), v1 = v0;
                if (gr < N_NODES) {
                    const float* ap = &((const float*)A)[(size_t)gr * lda + ch * 64 + g * 8];
                    v0 = *(const float4*)ap;
                    v1 = *(const float4*)(ap + 4);
                }
                __half h[8];
                h[0] = __float2half_rn(v0.x); h[1] = __float2half_rn(v0.y);
                h[2] = __float2half_rn(v0.z); h[3] = __float2half_rn(v0.w);
                h[4] = __float2half_rn(v1.x); h[5] = __float2half_rn(v1.y);
                h[6] = __float2half_rn(v1.z); h[7] = __float2half_rn(v1.w);
                *(uint4*)((char*)Ah + off) = *(const uint4*)h;
            }
        }
        __syncthreads();

        // ---- Compute: 4 k-steps of 16
#pragma unroll
        for (int ks = 0; ks < 4; ks++) {
            uint32_t afh[2][4], bfh[2][4];
#pragma unroll
            for (int mt = 0; mt < 2; mt++) {
                int arow = wm * 32 + mt * 16 + a_lrow;
                uint32_t a_off = arow * 128u +
                                 (((uint32_t)((ks * 2 + a_gad) ^ (arow & 7))) << 4);
                ldsm4(afh[mt], ah_u + a_off);
            }
#pragma unroll
            for (int bt = 0; bt < 2; bt++) {
                int brow = wn * 32 + bt * 16 + b_lr;
                uint32_t b_off = brow * 128u +
                                 (((uint32_t)((ks * 2 + b_gad) ^ (brow & 7))) << 4);
                ldsm4(bfh[bt], bh_u + b_off);
            }
#pragma unroll
            for (int mt = 0; mt < 2; mt++)
#pragma unroll
                for (int bt = 0; bt < 2; bt++) {
                    mma16816(acc[mt][bt * 2 + 0], afh[mt], bfh[bt][0], bfh[bt][1]);
                    mma16816(acc[mt][bt * 2 + 1], afh[mt], bfh[bt][2], bfh[bt][3]);
                }
        }
        __syncthreads();
    }

    // ---- Unified fp16 epilogue: stage, then coalesced 16B stores
    const int ccol = (lane & 3) * 2;
#pragma unroll
    for (int mt = 0; mt < 2; mt++) {
        int lrow0 = wm * 32 + mt * 16 + (lane >> 2);
#pragma unroll
        for (int j = 0; j < 4; j++) {
            int lc = wn * 32 + j * 8 + ccol;
            *(__half2*)&stage[lrow0 * STG_STRIDE + lc] =
                __floats2half2_rn(acc[mt][j][0], acc[mt][j][1]);
            *(__half2*)&stage[(lrow0 + 8) * STG_STRIDE + lc] =
                __floats2half2_rn(acc[mt][j][2], acc[mt][j][3]);
        }
    }
    __syncthreads();
    __half* dstbuf = (cb == 0) ? Cacc : Cmsg;
    const int dstride = (cb == 0) ? ACC_COLS : MSG_COLS;
    const int mbase = (cb == 0) ? 0 : (cb - 1) * 64;
#pragma unroll
    for (int i = 0; i < 4; i++) {
        int chunk = i * 256 + tid;      // 1024 chunks of 16 B
        int row = chunk >> 3;
        int cc  = chunk & 7;
        int gr = m0 + row;
        if (gr < N_NODES) {
            uint4 v = *(const uint4*)&stage[row * STG_STRIDE + cc * 8];
            *(uint4*)&dstbuf[(size_t)gr * dstride + mbase + cc * 8] = v;
        }
    }
}

// ---------------------------------------------------------------------------
// Aggregate: acc[n] += sum of msg[elist[i]]; optional fused relu.
// 8 threads per node; 2-deep unrolled gathers (MLP=2); f32 register accum.
// ---------------------------------------------------------------------------
__device__ __forceinline__ void add8(float4& a0, float4& a1, uint4 g) {
    __half2* h = (__half2*)&g;
    float2 f0 = __half22float2(h[0]), f1 = __half22float2(h[1]);
    float2 f2 = __half22float2(h[2]), f3 = __half22float2(h[3]);
    a0.x += f0.x; a0.y += f0.y; a0.z += f1.x; a0.w += f1.y;
    a1.x += f2.x; a1.y += f2.y; a1.z += f3.x; a1.w += f3.y;
}

template <bool RELU>
__global__ void __launch_bounds__(256) agg_kernel(const int* __restrict__ starts,
                                                  const int* __restrict__ elist,
                                                  const __half* __restrict__ msg,
                                                  __half* __restrict__ acc) {
    int gid = blockIdx.x * blockDim.x + threadIdx.x;
    int n   = gid >> 3;
    if (n >= N_NODES) return;
    int sub = gid & 7;

    int beg = __ldg(&starts[n]);
    int end = __ldg(&starts[n + 1]);

    __half* ap = &acc[(size_t)n * ACC_COLS + sub * 8];
    uint4 aw = *(const uint4*)ap;
    float4 a0 = make_float4(0.f, 0.f, 0.f, 0.f), a1 = a0;
    add8(a0, a1, aw);   // self-path from gemm cb0

    int i = beg;
    for (; i + 1 < end; i += 2) {
        int o0 = __ldg(&elist[i]);
        int o1 = __ldg(&elist[i + 1]);
        uint4 g0 = *(const uint4*)&msg[(size_t)o0 + sub * 8];
        uint4 g1 = *(const uint4*)&msg[(size_t)o1 + sub * 8];
        add8(a0, a1, g0);
        add8(a0, a1, g1);
    }
    if (i < end) {
        int o0 = __ldg(&elist[i]);
        uint4 g0 = *(const uint4*)&msg[(size_t)o0 + sub * 8];
        add8(a0, a1, g0);
    }

    if (RELU) {
        a0.x = fmaxf(a0.x, 0.f); a0.y = fmaxf(a0.y, 0.f);
        a0.z = fmaxf(a0.z, 0.f); a0.w = fmaxf(a0.w, 0.f);
        a1.x = fmaxf(a1.x, 0.f); a1.y = fmaxf(a1.y, 0.f);
        a1.z = fmaxf(a1.z, 0.f); a1.w = fmaxf(a1.w, 0.f);
    }
    __half h[8];
    h[0] = __float2half_rn(a0.x); h[1] = __float2half_rn(a0.y);
    h[2] = __float2half_rn(a0.z); h[3] = __float2half_rn(a0.w);
    h[4] = __float2half_rn(a1.x); h[5] = __float2half_rn(a1.y);
    h[6] = __float2half_rn(a1.z); h[7] = __float2half_rn(a1.w);
    *(uint4*)ap = *(const uint4*)h;
}

// ---------------------------------------------------------------------------
// out = sigmoid(relu(acc2))  — fp16 in, f32 out, fully contiguous
// ---------------------------------------------------------------------------
__global__ void __launch_bounds__(256) sigmoid_kernel(const __half* __restrict__ acc,
                                                      float* __restrict__ out) {
    int idx = blockIdx.x * blockDim.x + threadIdx.x;   // over N*8 groups of 8 halves
    if (idx >= N_NODES * 8) return;
    uint4 g = *(const uint4*)&acc[(size_t)idx * 8];
    __half2* h = (__half2*)&g;
    float r[8];
    float2 f0 = __half22float2(h[0]), f1 = __half22float2(h[1]);
    float2 f2 = __half22float2(h[2]), f3 = __half22float2(h[3]);
    r[0] = f0.x; r[1] = f0.y; r[2] = f1.x; r[3] = f1.y;
    r[4] = f2.x; r[5] = f2.y; r[6] = f3.x; r[7] = f3.y;
#pragma unroll
    for (int j = 0; j < 8; j++)
        r[j] = 1.f / (1.f + __expf(-fmaxf(r[j], 0.f)));
    float4* op = (float4*)&out[(size_t)idx * 8];
    op[0] = make_float4(r[0], r[1], r[2], r[3]);
    op[1] = make_float4(r[4], r[5], r[6], r[7]);
}

// ---------------------------------------------------------------------------
extern "C" void kernel_launch(void* const* d_in, const int* in_sizes, int n_in,
                              void* d_out, int out_size) {
    const float* node_emb = (const float*)d_in[0];
    const void*  src      = d_in[1];
    const void*  dst      = d_in[2];
    const float* W1       = (const float*)d_in[3];
    const float* Wself1   = (const float*)d_in[4];
    const float* W2       = (const float*)d_in[5];
    const float* Wself2   = (const float*)d_in[6];
    float*       out      = (float*)d_out;

    __half *acc1, *acc2, *msg1, *msg2, *B1, *B2;
    int *counts, *starts, *cursor, *bsum, *elist;
    cudaGetSymbolAddress((void**)&acc1, g_acc1);
    cudaGetSymbolAddress((void**)&acc2, g_acc2);
    cudaGetSymbolAddress((void**)&msg1, g_msg1);
    cudaGetSymbolAddress((void**)&msg2, g_msg2);
    cudaGetSymbolAddress((void**)&B1, g_B1);
    cudaGetSymbolAddress((void**)&B2, g_B2);
    cudaGetSymbolAddress((void**)&counts, g_counts);
    cudaGetSymbolAddress((void**)&starts, g_starts);
    cudaGetSymbolAddress((void**)&cursor, g_cursor);
    cudaGetSymbolAddress((void**)&bsum, g_bsum);
    cudaGetSymbolAddress((void**)&elist, g_elist);

    const int eblocks = (E_TOTAL + 255) / 256;
    const int nb1024  = (N_NODES + 1023) / 1024;           // 98

    // ---- dtype sniff + dst-sorted edge list (per launch; graph-capturable)
    sniff_kernel<<<1, 256>>>((const unsigned int*)src);
    cudaMemsetAsync(counts, 0, N_NODES * sizeof(int));
    count_kernel<<<eblocks, 256>>>(dst, counts);
    scan1_kernel<<<nb1024, 256>>>(counts, starts, bsum);
    scan2_kernel<<<1, 128>>>(bsum, nb1024);
    scan3_kernel<<<(N_NODES + 256) / 256, 256>>>(starts, cursor, bsum);
    fill_kernel<<<eblocks, 256>>>(src, dst, cursor, elist);

    // ---- weights
    prep_w_kernel<<<(320 * 128 + 320 * 64 + 255) / 256, 256>>>(W1, Wself1, W2, Wself2, B1, B2);

    const int mblocks = (N_NODES + 127) / 128;             // 782
    const int ablocks = (N_NODES * 8 + 255) / 256;         // 3125

    // Layer 1: acc1/msg1 = node_emb @ Wc1; aggregate + relu into acc1 (fp16)
    gemm_mma_kernel<2, false><<<dim3(5, mblocks), 256>>>(node_emb, 128, B1, acc1, msg1);
    agg_kernel<true><<<ablocks, 256>>>(starts, elist, msg1, acc1);

    // Layer 2: acc2/msg2 = acc1(fp16) @ Wc2; aggregate into acc2 (no relu)
    gemm_mma_kernel<1, true><<<dim3(5, mblocks), 256>>>(acc1, ACC_COLS, B2, acc2, msg2);
    agg_kernel<false><<<ablocks, 256>>>(starts, elist, msg2, acc2);

    // out = sigmoid(relu(acc2))
    sigmoid_kernel<<<(N_NODES * 8 + 255) / 256, 256>>>(acc2, out);
}